// round 1
// baseline (speedup 1.0000x reference)
#include <cuda_runtime.h>
#include <math.h>

// Problem constants
#define BATCH 8
#define CIN   192
#define HIMG  128
#define WIMG  128
#define HW    16384           // 128*128
#define MTOT  131072          // BATCH*HW
#define NQKV  576             // 3*C
#define NH    6
#define HD    32
#define WS    8
#define NWIN  64              // WS*WS
#define SCALE 0.17677669529663687f   // 32^-0.5

// ---------------- scratch (device globals; no runtime allocation) -----------
__device__ float d_qkv[(size_t)MTOT * NQKV];     // [pixel][576]  q|k|v channel-contig
__device__ float d_yb [(size_t)MTOT * CIN];      // [pixel][192]
__device__ float d_wfused[NQKV * CIN];           // [576][192]
__device__ float d_bfused[NQKV];
__device__ float d_biasT[NH * NWIN * NWIN];      // [head][n][m]

// ---------------- kernel 1: fuse QK_w/V_w into one weight matrix ------------
__global__ void fuse_w_kernel(const float* __restrict__ QK_w,
                              const float* __restrict__ QK_b,
                              const float* __restrict__ V_w,
                              const float* __restrict__ V_b) {
    int idx = blockIdx.x * blockDim.x + threadIdx.x;
    if (idx < NQKV * CIN) {
        int n = idx / CIN, k = idx - n * CIN;
        d_wfused[idx] = (n < 2 * CIN) ? QK_w[n * CIN + k] : V_w[(n - 2 * CIN) * CIN + k];
    }
    if (idx < NQKV) {
        d_bfused[idx] = (idx < 2 * CIN) ? QK_b[idx] : V_b[idx - 2 * CIN];
    }
}

// ---------------- kernel 2: relative-position bias via meta MLP -------------
// bias[h][n1][n2] = relu(rp(n1,n2) @ W1 + b1) @ W2 + b2
__global__ void bias_kernel(const float* __restrict__ w1, const float* __restrict__ b1,
                            const float* __restrict__ w2, const float* __restrict__ b2) {
    int idx = blockIdx.x * 256 + threadIdx.x;   // 0..4095
    if (idx >= NWIN * NWIN) return;
    int n1 = idx >> 6, n2 = idx & 63;
    float di = (float)((n1 >> 3) - (n2 >> 3));
    float dj = (float)((n1 & 7) - (n2 & 7));
    float s0 = (di > 0.f) ? 1.f : ((di < 0.f) ? -1.f : 0.f);
    float s1 = (dj > 0.f) ? 1.f : ((dj < 0.f) ? -1.f : 0.f);
    float rp0 = s0 * log1pf(fabsf(di));
    float rp1 = s1 * log1pf(fabsf(dj));
    float acc[NH];
#pragma unroll
    for (int c = 0; c < NH; c++) acc[c] = b2[c];
    for (int t = 0; t < 256; t++) {
        float h = rp0 * w1[t] + rp1 * w1[256 + t] + b1[t];
        h = fmaxf(h, 0.f);
#pragma unroll
        for (int c = 0; c < NH; c++) acc[c] += h * w2[t * NH + c];
    }
#pragma unroll
    for (int c = 0; c < NH; c++)
        d_biasT[(c * NWIN + n1) * NWIN + n2] = acc[c];
}

// ---------------- kernel 3: GEMM1 qkv = x @ Wfused^T + bfused ---------------
// A[m,k] = x[b, k, hw]  (k-strided, m-contiguous)   M=131072, N=576, K=192
// C row-major [m][576] -> d_qkv
__global__ void __launch_bounds__(256) gemm_qkv_kernel(const float* __restrict__ x) {
    __shared__ float As[16][128];
    __shared__ float Bs[16][68];

    int m0 = blockIdx.y * 128;
    int n0 = blockIdx.x * 64;
    int b  = m0 >> 14;
    int hw0 = m0 & (HW - 1);
    const float* xb = x + (size_t)b * CIN * HW + hw0;

    int t = threadIdx.x;
    int la_k = t >> 5;            // 0..7
    int la_m = (t & 31) << 2;     // 0..124
    int lb_n = t >> 2;            // 0..63
    int lb_k = (t & 3) << 2;      // 0,4,8,12
    int tm = (t & 15) << 2;       // 0..60
    int tn = (t >> 4) << 2;       // 0..60

    float acc[8][4];
#pragma unroll
    for (int i = 0; i < 8; i++)
#pragma unroll
        for (int j = 0; j < 4; j++) acc[i][j] = 0.f;

    for (int k0 = 0; k0 < CIN; k0 += 16) {
        __syncthreads();
#pragma unroll
        for (int r = 0; r < 2; r++) {
            int kk = la_k + r * 8;
            float4 v = *(const float4*)(xb + (size_t)(k0 + kk) * HW + la_m);
            *(float4*)&As[kk][la_m] = v;
        }
        {
            float4 v = *(const float4*)(&d_wfused[(n0 + lb_n) * CIN + k0 + lb_k]);
            Bs[lb_k + 0][lb_n] = v.x;
            Bs[lb_k + 1][lb_n] = v.y;
            Bs[lb_k + 2][lb_n] = v.z;
            Bs[lb_k + 3][lb_n] = v.w;
        }
        __syncthreads();
#pragma unroll
        for (int kk = 0; kk < 16; kk++) {
            float4 a0 = *(float4*)&As[kk][tm];
            float4 a1 = *(float4*)&As[kk][tm + 64];
            float4 bv = *(float4*)&Bs[kk][tn];
            float av[8] = {a0.x, a0.y, a0.z, a0.w, a1.x, a1.y, a1.z, a1.w};
            float bw[4] = {bv.x, bv.y, bv.z, bv.w};
#pragma unroll
            for (int i = 0; i < 8; i++)
#pragma unroll
                for (int j = 0; j < 4; j++) acc[i][j] += av[i] * bw[j];
        }
    }

    float4 bb = *(float4*)&d_bfused[n0 + tn];
#pragma unroll
    for (int i = 0; i < 8; i++) {
        int m = m0 + ((i < 4) ? (tm + i) : (64 + tm + i - 4));
        float4 o;
        o.x = acc[i][0] + bb.x;
        o.y = acc[i][1] + bb.y;
        o.z = acc[i][2] + bb.z;
        o.w = acc[i][3] + bb.w;
        *(float4*)&d_qkv[(size_t)m * NQKV + n0 + tn] = o;
    }
}

// ---------------- kernel 4: windowed attention with circular-conv modulation
// block = (window w_, head). 256 threads.
__global__ void __launch_bounds__(256) attn_kernel() {
    __shared__ float qs[HD][65];   // d-major; reused as o[d][n] after conv
    __shared__ float ks[HD][65];
    __shared__ float vs[HD][65];
    __shared__ float ps[NWIN][66];
    __shared__ float rinv[NWIN];

    int w_  = blockIdx.x;
    int head = blockIdx.y;
    int t = threadIdx.x;

    int b   = w_ >> 8;
    int rem = w_ & 255;
    int wi  = rem >> 4, wj = rem & 15;
    int base_pix = b * HW + wi * 8 * WIMG + wj * 8;
    int chq = head * HD;

    // ---- load q,k,v for this (window, head); q scaled ----
#pragma unroll
    for (int r = 0; r < 2; r++) {
        int idx = t + r * 256;             // 0..511
        int n  = idx >> 3;
        int dq = (idx & 7) << 2;           // 0..28
        int m = base_pix + ((n >> 3) * WIMG) + (n & 7);
        const float* p = d_qkv + (size_t)m * NQKV + chq + dq;
        float4 qv = *(const float4*)(p);
        float4 kv = *(const float4*)(p + CIN);
        float4 vv = *(const float4*)(p + 2 * CIN);
        qs[dq + 0][n] = qv.x * SCALE; qs[dq + 1][n] = qv.y * SCALE;
        qs[dq + 2][n] = qv.z * SCALE; qs[dq + 3][n] = qv.w * SCALE;
        ks[dq + 0][n] = kv.x; ks[dq + 1][n] = kv.y;
        ks[dq + 2][n] = kv.z; ks[dq + 3][n] = kv.w;
        vs[dq + 0][n] = vv.x; vs[dq + 1][n] = vv.y;
        vs[dq + 2][n] = vv.z; vs[dq + 3][n] = vv.w;
    }
    __syncthreads();

    // ---- 8x8 circular conv per channel: o[i,j,d] = sum q[a,b,d] k[(i-a)%8,(j-b)%8,d]
    int ci = t & 7;        // output row i
    int d  = t >> 3;       // channel (0..31)
    float oacc[8];
#pragma unroll
    for (int j = 0; j < 8; j++) oacc[j] = 0.f;
#pragma unroll
    for (int ai = 0; ai < 8; ai++) {
        int ki = (ci - ai) & 7;
        float kr[8];
#pragma unroll
        for (int jj = 0; jj < 8; jj++) kr[jj] = ks[d][ki * 8 + jj];
#pragma unroll
        for (int aj = 0; aj < 8; aj++) {
            float qv = qs[d][ai * 8 + aj];
#pragma unroll
            for (int j = 0; j < 8; j++) oacc[j] += qv * kr[(j - aj) & 7];
        }
    }
    __syncthreads();
    // store o into qs (q no longer needed): qs[d][n] = o[n][d]
#pragma unroll
    for (int j = 0; j < 8; j++) qs[d][ci * 8 + j] = oacc[j];
    __syncthreads();

    // ---- logits s[n][m] = sum_d o[n][d] v[m][d] + bias[h][n][m]; softmax over m
    int n0 = (t >> 4) << 2;    // 0..60
    int m0 = (t & 15) << 2;    // 0..60
    float s[4][4];
#pragma unroll
    for (int a = 0; a < 4; a++)
#pragma unroll
        for (int c = 0; c < 4; c++) s[a][c] = 0.f;
    for (int dd = 0; dd < HD; dd++) {
        float ov[4], vv4[4];
#pragma unroll
        for (int c = 0; c < 4; c++) ov[c]  = qs[dd][n0 + c];
#pragma unroll
        for (int c = 0; c < 4; c++) vv4[c] = vs[dd][m0 + c];
#pragma unroll
        for (int a = 0; a < 4; a++)
#pragma unroll
            for (int c = 0; c < 4; c++) s[a][c] += ov[a] * vv4[c];
    }
    const float* bp = d_biasT + head * NWIN * NWIN;
#pragma unroll
    for (int a = 0; a < 4; a++) {
#pragma unroll
        for (int c = 0; c < 4; c++) s[a][c] += bp[(n0 + a) * NWIN + m0 + c];
    }
    // softmax: reduce over the 16 lanes that share n-group (lanes t&15)
#pragma unroll
    for (int a = 0; a < 4; a++) {
        float mx = fmaxf(fmaxf(s[a][0], s[a][1]), fmaxf(s[a][2], s[a][3]));
#pragma unroll
        for (int off = 1; off < 16; off <<= 1)
            mx = fmaxf(mx, __shfl_xor_sync(0xffffffffu, mx, off));
        float e0 = __expf(s[a][0] - mx);
        float e1 = __expf(s[a][1] - mx);
        float e2 = __expf(s[a][2] - mx);
        float e3 = __expf(s[a][3] - mx);
        float sm = e0 + e1 + e2 + e3;
#pragma unroll
        for (int off = 1; off < 16; off <<= 1)
            sm += __shfl_xor_sync(0xffffffffu, sm, off);
        ps[n0 + a][m0 + 0] = e0;
        ps[n0 + a][m0 + 1] = e1;
        ps[n0 + a][m0 + 2] = e2;
        ps[n0 + a][m0 + 3] = e3;
        if ((t & 15) == 0) rinv[n0 + a] = 1.f / sm;
    }
    __syncthreads();

    // ---- y[n][d] = (1/sum) * sum_m p[n][m] v[m][d]
    int n0b = (t >> 4) << 2;   // 4 rows
    int d0  = (t & 15) << 1;   // 2 channels
    float y[4][2];
#pragma unroll
    for (int a = 0; a < 4; a++) { y[a][0] = 0.f; y[a][1] = 0.f; }
    for (int mm = 0; mm < NWIN; mm++) {
        float v0 = vs[d0][mm], v1 = vs[d0 + 1][mm];
#pragma unroll
        for (int a = 0; a < 4; a++) {
            float pv = ps[n0b + a][mm];
            y[a][0] += pv * v0;
            y[a][1] += pv * v1;
        }
    }
#pragma unroll
    for (int a = 0; a < 4; a++) {
        int n = n0b + a;
        float ri = rinv[n];
        int m = base_pix + ((n >> 3) * WIMG) + (n & 7);
        float2 o2;
        o2.x = y[a][0] * ri;
        o2.y = y[a][1] * ri;
        *(float2*)&d_yb[(size_t)m * CIN + head * HD + d0] = o2;
    }
}

// ---------------- kernel 5: GEMM2 out = yb @ proj_w^T + proj_b --------------
// A[m,k] = yb[m][k] (k-contiguous).  C -> out[b, n, hw] (m-contiguous per n)
__global__ void __launch_bounds__(256) gemm_proj_kernel(const float* __restrict__ pw,
                                                        const float* __restrict__ pb,
                                                        float* __restrict__ out) {
    __shared__ float As[16][128];
    __shared__ float Bs[16][68];

    int m0 = blockIdx.y * 128;
    int n0 = blockIdx.x * 64;
    int b  = m0 >> 14;
    int hw0 = m0 & (HW - 1);

    int t = threadIdx.x;
    int la_m = t >> 1;            // 0..127
    int la_kh = (t & 1) << 3;     // 0 or 8
    int lb_n = t >> 2;            // 0..63
    int lb_k = (t & 3) << 2;      // 0,4,8,12
    int tm = (t & 15) << 2;
    int tn = (t >> 4) << 2;

    float acc[8][4];
#pragma unroll
    for (int i = 0; i < 8; i++)
#pragma unroll
        for (int j = 0; j < 4; j++) acc[i][j] = 0.f;

    for (int k0 = 0; k0 < CIN; k0 += 16) {
        __syncthreads();
        {
            const float* ap = d_yb + (size_t)(m0 + la_m) * CIN + k0 + la_kh;
            float4 v0 = *(const float4*)(ap);
            float4 v1 = *(const float4*)(ap + 4);
            As[la_kh + 0][la_m] = v0.x; As[la_kh + 1][la_m] = v0.y;
            As[la_kh + 2][la_m] = v0.z; As[la_kh + 3][la_m] = v0.w;
            As[la_kh + 4][la_m] = v1.x; As[la_kh + 5][la_m] = v1.y;
            As[la_kh + 6][la_m] = v1.z; As[la_kh + 7][la_m] = v1.w;
        }
        {
            float4 v = *(const float4*)(&pw[(n0 + lb_n) * CIN + k0 + lb_k]);
            Bs[lb_k + 0][lb_n] = v.x;
            Bs[lb_k + 1][lb_n] = v.y;
            Bs[lb_k + 2][lb_n] = v.z;
            Bs[lb_k + 3][lb_n] = v.w;
        }
        __syncthreads();
#pragma unroll
        for (int kk = 0; kk < 16; kk++) {
            float4 a0 = *(float4*)&As[kk][tm];
            float4 a1 = *(float4*)&As[kk][tm + 64];
            float4 bv = *(float4*)&Bs[kk][tn];
            float av[8] = {a0.x, a0.y, a0.z, a0.w, a1.x, a1.y, a1.z, a1.w};
            float bw[4] = {bv.x, bv.y, bv.z, bv.w};
#pragma unroll
            for (int i = 0; i < 8; i++)
#pragma unroll
                for (int j = 0; j < 4; j++) acc[i][j] += av[i] * bw[j];
        }
    }

#pragma unroll
    for (int j = 0; j < 4; j++) {
        int n = n0 + tn + j;
        float bias = pb[n];
        float* obase = out + (size_t)(b * CIN + n) * HW + hw0;
        float4 v0, v1;
        v0.x = acc[0][j] + bias; v0.y = acc[1][j] + bias;
        v0.z = acc[2][j] + bias; v0.w = acc[3][j] + bias;
        v1.x = acc[4][j] + bias; v1.y = acc[5][j] + bias;
        v1.z = acc[6][j] + bias; v1.w = acc[7][j] + bias;
        *(float4*)(obase + tm) = v0;
        *(float4*)(obase + 64 + tm) = v1;
    }
}

// ---------------- launch -----------------------------------------------------
extern "C" void kernel_launch(void* const* d_in, const int* in_sizes, int n_in,
                              void* d_out, int out_size) {
    const float* x      = (const float*)d_in[0];
    const float* V_w    = (const float*)d_in[1];
    const float* V_b    = (const float*)d_in[2];
    const float* QK_w   = (const float*)d_in[3];
    const float* QK_b   = (const float*)d_in[4];
    const float* proj_w = (const float*)d_in[5];
    const float* proj_b = (const float*)d_in[6];
    const float* mw1    = (const float*)d_in[7];
    const float* mb1    = (const float*)d_in[8];
    const float* mw2    = (const float*)d_in[9];
    const float* mb2    = (const float*)d_in[10];
    float* out = (float*)d_out;

    fuse_w_kernel<<<(NQKV * CIN + 255) / 256, 256>>>(QK_w, QK_b, V_w, V_b);
    bias_kernel<<<(NWIN * NWIN + 255) / 256, 256>>>(mw1, mb1, mw2, mb2);
    gemm_qkv_kernel<<<dim3(NQKV / 64, MTOT / 128), 256>>>(x);
    attn_kernel<<<dim3(2048, NH), 256>>>();
    gemm_proj_kernel<<<dim3(CIN / 64, MTOT / 128), 256>>>(proj_w, proj_b, out);
}

// round 3
// speedup vs baseline: 1.5249x; 1.5249x over previous
#include <cuda_runtime.h>
#include <math.h>
#include <stdint.h>

// Problem constants
#define BATCH 8
#define CIN   192
#define HIMG  128
#define WIMG  128
#define HW    16384           // 128*128
#define MTOT  131072          // BATCH*HW
#define NQKV  576             // 3*C
#define NH    6
#define HD    32
#define WS    8
#define NWIN  64              // WS*WS
#define SCALE 0.17677669529663687f   // 32^-0.5

// ---------------- scratch (device globals; no runtime allocation) -----------
__device__ float d_qkv[(size_t)MTOT * NQKV];     // [pixel][576]  q|k|v channel-contig
__device__ float d_yb [(size_t)MTOT * CIN];      // [pixel][192]
__device__ float d_wfused[NQKV * CIN];           // [576][192]
__device__ float d_bfused[NQKV];
__device__ float d_biasT[NH * NWIN * NWIN];      // [head][n][m]

// ---------------- tf32 helpers ----------------------------------------------
__device__ __forceinline__ uint32_t f2tf(float f) {
    uint32_t u;
    asm("cvt.rna.tf32.f32 %0, %1;" : "=r"(u) : "f"(f));
    return u;
}

__device__ __forceinline__ void mma_tf32(float c[4], const uint32_t a[4], const uint32_t b[2]) {
    asm volatile(
        "mma.sync.aligned.m16n8k8.row.col.f32.tf32.tf32.f32 "
        "{%0,%1,%2,%3}, {%4,%5,%6,%7}, {%8,%9}, {%0,%1,%2,%3};"
        : "+f"(c[0]), "+f"(c[1]), "+f"(c[2]), "+f"(c[3])
        : "r"(a[0]), "r"(a[1]), "r"(a[2]), "r"(a[3]), "r"(b[0]), "r"(b[1]));
}

// ---------------- kernel 1: fuse QK_w/V_w into one weight matrix ------------
__global__ void fuse_w_kernel(const float* __restrict__ QK_w,
                              const float* __restrict__ QK_b,
                              const float* __restrict__ V_w,
                              const float* __restrict__ V_b) {
    int idx = blockIdx.x * blockDim.x + threadIdx.x;
    if (idx < NQKV * CIN) {
        int n = idx / CIN, k = idx - n * CIN;
        d_wfused[idx] = (n < 2 * CIN) ? QK_w[n * CIN + k] : V_w[(n - 2 * CIN) * CIN + k];
    }
    if (idx < NQKV) {
        d_bfused[idx] = (idx < 2 * CIN) ? QK_b[idx] : V_b[idx - 2 * CIN];
    }
}

// ---------------- kernel 2: relative-position bias via meta MLP -------------
__global__ void bias_kernel(const float* __restrict__ w1, const float* __restrict__ b1,
                            const float* __restrict__ w2, const float* __restrict__ b2) {
    int idx = blockIdx.x * 256 + threadIdx.x;   // 0..4095
    if (idx >= NWIN * NWIN) return;
    int n1 = idx >> 6, n2 = idx & 63;
    float di = (float)((n1 >> 3) - (n2 >> 3));
    float dj = (float)((n1 & 7) - (n2 & 7));
    float s0 = (di > 0.f) ? 1.f : ((di < 0.f) ? -1.f : 0.f);
    float s1 = (dj > 0.f) ? 1.f : ((dj < 0.f) ? -1.f : 0.f);
    float rp0 = s0 * log1pf(fabsf(di));
    float rp1 = s1 * log1pf(fabsf(dj));
    float acc[NH];
#pragma unroll
    for (int c = 0; c < NH; c++) acc[c] = b2[c];
    for (int t = 0; t < 256; t++) {
        float h = rp0 * w1[t] + rp1 * w1[256 + t] + b1[t];
        h = fmaxf(h, 0.f);
#pragma unroll
        for (int c = 0; c < NH; c++) acc[c] += h * w2[t * NH + c];
    }
#pragma unroll
    for (int c = 0; c < NH; c++)
        d_biasT[(c * NWIN + n1) * NWIN + n2] = acc[c];
}

// ---------------- kernel 3: GEMM1 (tf32 tensor core) ------------------------
// qkv[m][n] = sum_k x[b][k][hw] * Wfused[n][k] + bfused[n]
// M=131072, N=576, K=192. Block tile 128x64, BK=32, 8 warps (each 32x32).
#define G1_SA_STRIDE 136
#define G1_SB_STRIDE 72
__global__ void __launch_bounds__(256) gemm_qkv_tc(const float* __restrict__ x) {
    __shared__ __align__(16) uint32_t sh[32 * G1_SA_STRIDE + 32 * G1_SB_STRIDE];
    uint32_t* sA = sh;
    uint32_t* sB = sh + 32 * G1_SA_STRIDE;

    int m0 = blockIdx.y * 128;
    int n0 = blockIdx.x * 64;
    int b  = m0 >> 14;
    int hw0 = m0 & (HW - 1);
    const float* xb = x + (size_t)b * CIN * HW + hw0;

    int t = threadIdx.x;
    int lane = t & 31, warp = t >> 5;
    int wm = (warp >> 1) << 5;   // 0,32,64,96
    int wn = (warp & 1) << 5;    // 0,32

    int ak = t >> 5;             // k row 0..7 (+8r)
    int am = (t & 31) << 2;      // m vec
    int bn = t >> 3;             // n 0..31 (+32r)
    int bk = (t & 7) << 2;       // k vec

    float4 ra[4];
    float4 rb[2];
#pragma unroll
    for (int r = 0; r < 4; r++)
        ra[r] = *(const float4*)(xb + (size_t)(ak + r * 8) * HW + am);
#pragma unroll
    for (int r = 0; r < 2; r++)
        rb[r] = *(const float4*)(d_wfused + (size_t)(n0 + bn + r * 32) * CIN + bk);

    float c[2][4][4];
#pragma unroll
    for (int i = 0; i < 2; i++)
#pragma unroll
        for (int j = 0; j < 4; j++)
#pragma unroll
            for (int q = 0; q < 4; q++) c[i][j][q] = 0.f;

    for (int k0 = 0; k0 < CIN; k0 += 32) {
#pragma unroll
        for (int r = 0; r < 4; r++) {
            uint32_t* p = sA + (ak + r * 8) * G1_SA_STRIDE + am;
            p[0] = f2tf(ra[r].x); p[1] = f2tf(ra[r].y);
            p[2] = f2tf(ra[r].z); p[3] = f2tf(ra[r].w);
        }
#pragma unroll
        for (int r = 0; r < 2; r++) {
            int n = bn + r * 32;
            sB[(bk + 0) * G1_SB_STRIDE + n] = f2tf(rb[r].x);
            sB[(bk + 1) * G1_SB_STRIDE + n] = f2tf(rb[r].y);
            sB[(bk + 2) * G1_SB_STRIDE + n] = f2tf(rb[r].z);
            sB[(bk + 3) * G1_SB_STRIDE + n] = f2tf(rb[r].w);
        }
        __syncthreads();
        if (k0 + 32 < CIN) {
#pragma unroll
            for (int r = 0; r < 4; r++)
                ra[r] = *(const float4*)(xb + (size_t)(k0 + 32 + ak + r * 8) * HW + am);
#pragma unroll
            for (int r = 0; r < 2; r++)
                rb[r] = *(const float4*)(d_wfused + (size_t)(n0 + bn + r * 32) * CIN + k0 + 32 + bk);
        }
#pragma unroll
        for (int kk = 0; kk < 32; kk += 8) {
            uint32_t a[2][4], bfr[4][2];
#pragma unroll
            for (int i = 0; i < 2; i++) {
                int row = wm + i * 16 + (lane >> 2);
                int kc  = kk + (lane & 3);
                a[i][0] = sA[kc * G1_SA_STRIDE + row];
                a[i][1] = sA[kc * G1_SA_STRIDE + row + 8];
                a[i][2] = sA[(kc + 4) * G1_SA_STRIDE + row];
                a[i][3] = sA[(kc + 4) * G1_SA_STRIDE + row + 8];
            }
#pragma unroll
            for (int j = 0; j < 4; j++) {
                int col = wn + j * 8 + (lane >> 2);
                int kr  = kk + (lane & 3);
                bfr[j][0] = sB[kr * G1_SB_STRIDE + col];
                bfr[j][1] = sB[(kr + 4) * G1_SB_STRIDE + col];
            }
#pragma unroll
            for (int i = 0; i < 2; i++)
#pragma unroll
                for (int j = 0; j < 4; j++)
                    mma_tf32(c[i][j], a[i], bfr[j]);
        }
        __syncthreads();
    }

#pragma unroll
    for (int i = 0; i < 2; i++) {
        int row0 = m0 + wm + i * 16 + (lane >> 2);
#pragma unroll
        for (int j = 0; j < 4; j++) {
            int col = n0 + wn + j * 8 + ((lane & 3) << 1);
            float b0 = d_bfused[col], b1 = d_bfused[col + 1];
            float2 v0 = {c[i][j][0] + b0, c[i][j][1] + b1};
            float2 v1 = {c[i][j][2] + b0, c[i][j][3] + b1};
            *(float2*)&d_qkv[(size_t)row0 * NQKV + col] = v0;
            *(float2*)&d_qkv[(size_t)(row0 + 8) * NQKV + col] = v1;
        }
    }
}

// ---------------- kernel 4: windowed attention with circular-conv modulation
__global__ void __launch_bounds__(256) attn_kernel() {
    __shared__ float qs[HD][65];   // d-major; reused as o[d][n] after conv
    __shared__ float ks[HD][65];
    __shared__ float vs[HD][65];
    __shared__ float ps[NWIN][66];
    __shared__ float rinv[NWIN];

    int w_  = blockIdx.x;
    int head = blockIdx.y;
    int t = threadIdx.x;

    int b   = w_ >> 8;
    int rem = w_ & 255;
    int wi  = rem >> 4, wj = rem & 15;
    int base_pix = b * HW + wi * 8 * WIMG + wj * 8;
    int chq = head * HD;

#pragma unroll
    for (int r = 0; r < 2; r++) {
        int idx = t + r * 256;             // 0..511
        int n  = idx >> 3;
        int dq = (idx & 7) << 2;           // 0..28
        int m = base_pix + ((n >> 3) * WIMG) + (n & 7);
        const float* p = d_qkv + (size_t)m * NQKV + chq + dq;
        float4 qv = *(const float4*)(p);
        float4 kv = *(const float4*)(p + CIN);
        float4 vv = *(const float4*)(p + 2 * CIN);
        qs[dq + 0][n] = qv.x * SCALE; qs[dq + 1][n] = qv.y * SCALE;
        qs[dq + 2][n] = qv.z * SCALE; qs[dq + 3][n] = qv.w * SCALE;
        ks[dq + 0][n] = kv.x; ks[dq + 1][n] = kv.y;
        ks[dq + 2][n] = kv.z; ks[dq + 3][n] = kv.w;
        vs[dq + 0][n] = vv.x; vs[dq + 1][n] = vv.y;
        vs[dq + 2][n] = vv.z; vs[dq + 3][n] = vv.w;
    }
    __syncthreads();

    // 8x8 circular conv per channel
    int ci = t & 7;
    int d  = t >> 3;
    float oacc[8];
#pragma unroll
    for (int j = 0; j < 8; j++) oacc[j] = 0.f;
#pragma unroll
    for (int ai = 0; ai < 8; ai++) {
        int ki = (ci - ai) & 7;
        float kr[8];
#pragma unroll
        for (int jj = 0; jj < 8; jj++) kr[jj] = ks[d][ki * 8 + jj];
#pragma unroll
        for (int aj = 0; aj < 8; aj++) {
            float qv = qs[d][ai * 8 + aj];
#pragma unroll
            for (int j = 0; j < 8; j++) oacc[j] += qv * kr[(j - aj) & 7];
        }
    }
    __syncthreads();
#pragma unroll
    for (int j = 0; j < 8; j++) qs[d][ci * 8 + j] = oacc[j];
    __syncthreads();

    // logits + softmax
    int n0 = (t >> 4) << 2;
    int m0 = (t & 15) << 2;
    float s[4][4];
#pragma unroll
    for (int a = 0; a < 4; a++)
#pragma unroll
        for (int c = 0; c < 4; c++) s[a][c] = 0.f;
    for (int dd = 0; dd < HD; dd++) {
        float ov[4], vv4[4];
#pragma unroll
        for (int c = 0; c < 4; c++) ov[c]  = qs[dd][n0 + c];
#pragma unroll
        for (int c = 0; c < 4; c++) vv4[c] = vs[dd][m0 + c];
#pragma unroll
        for (int a = 0; a < 4; a++)
#pragma unroll
            for (int c = 0; c < 4; c++) s[a][c] += ov[a] * vv4[c];
    }
    const float* bp = d_biasT + head * NWIN * NWIN;
#pragma unroll
    for (int a = 0; a < 4; a++) {
#pragma unroll
        for (int c = 0; c < 4; c++) s[a][c] += bp[(n0 + a) * NWIN + m0 + c];
    }
#pragma unroll
    for (int a = 0; a < 4; a++) {
        float mx = fmaxf(fmaxf(s[a][0], s[a][1]), fmaxf(s[a][2], s[a][3]));
#pragma unroll
        for (int off = 1; off < 16; off <<= 1)
            mx = fmaxf(mx, __shfl_xor_sync(0xffffffffu, mx, off));
        float e0 = __expf(s[a][0] - mx);
        float e1 = __expf(s[a][1] - mx);
        float e2 = __expf(s[a][2] - mx);
        float e3 = __expf(s[a][3] - mx);
        float sm = e0 + e1 + e2 + e3;
#pragma unroll
        for (int off = 1; off < 16; off <<= 1)
            sm += __shfl_xor_sync(0xffffffffu, sm, off);
        ps[n0 + a][m0 + 0] = e0;
        ps[n0 + a][m0 + 1] = e1;
        ps[n0 + a][m0 + 2] = e2;
        ps[n0 + a][m0 + 3] = e3;
        if ((t & 15) == 0) rinv[n0 + a] = 1.f / sm;
    }
    __syncthreads();

    // y = softmax(p) @ v
    int n0b = (t >> 4) << 2;
    int d0  = (t & 15) << 1;
    float y[4][2];
#pragma unroll
    for (int a = 0; a < 4; a++) { y[a][0] = 0.f; y[a][1] = 0.f; }
    for (int mm = 0; mm < NWIN; mm++) {
        float v0 = vs[d0][mm], v1 = vs[d0 + 1][mm];
#pragma unroll
        for (int a = 0; a < 4; a++) {
            float pv = ps[n0b + a][mm];
            y[a][0] += pv * v0;
            y[a][1] += pv * v1;
        }
    }
#pragma unroll
    for (int a = 0; a < 4; a++) {
        int n = n0b + a;
        float ri = rinv[n];
        int m = base_pix + ((n >> 3) * WIMG) + (n & 7);
        float2 o2;
        o2.x = y[a][0] * ri;
        o2.y = y[a][1] * ri;
        *(float2*)&d_yb[(size_t)m * CIN + head * HD + d0] = o2;
    }
}

// ---------------- kernel 5: GEMM2 (tf32 tensor core) ------------------------
// out[b][n][hw] = sum_k yb[m][k] * proj_w[n][k] + proj_b[n]
// M=131072, N=192, K=192. Block tile 128x64, BK=32, 8 warps.
#define G2_SA_STRIDE 36
#define G2_SB_STRIDE 72
#define G2_SH_WORDS  8448   // >= max(128*36+32*72=6912, 128*65=8320)
__global__ void __launch_bounds__(256) gemm_proj_tc(const float* __restrict__ pw,
                                                    const float* __restrict__ pb,
                                                    float* __restrict__ out) {
    __shared__ __align__(16) uint32_t sh[G2_SH_WORDS];
    uint32_t* sA = sh;
    uint32_t* sB = sh + 128 * G2_SA_STRIDE;

    int m0 = blockIdx.y * 128;
    int n0 = blockIdx.x * 64;
    int b  = m0 >> 14;
    int hw0 = m0 & (HW - 1);

    int t = threadIdx.x;
    int lane = t & 31, warp = t >> 5;
    int wm = (warp >> 1) << 5;
    int wn = (warp & 1) << 5;

    int am = t >> 3;             // m 0..31 (+32r)
    int akq = (t & 7) << 2;      // k vec
    int bn = t >> 3;             // n 0..31 (+32r)
    int bk = (t & 7) << 2;       // k vec

    float4 ra[4];
    float4 rb[2];
#pragma unroll
    for (int r = 0; r < 4; r++)
        ra[r] = *(const float4*)(d_yb + (size_t)(m0 + am + r * 32) * CIN + akq);
#pragma unroll
    for (int r = 0; r < 2; r++)
        rb[r] = *(const float4*)(pw + (size_t)(n0 + bn + r * 32) * CIN + bk);

    float c[2][4][4];
#pragma unroll
    for (int i = 0; i < 2; i++)
#pragma unroll
        for (int j = 0; j < 4; j++)
#pragma unroll
            for (int q = 0; q < 4; q++) c[i][j][q] = 0.f;

    for (int k0 = 0; k0 < CIN; k0 += 32) {
#pragma unroll
        for (int r = 0; r < 4; r++) {
            uint32_t* p = sA + (am + r * 32) * G2_SA_STRIDE + akq;
            p[0] = f2tf(ra[r].x); p[1] = f2tf(ra[r].y);
            p[2] = f2tf(ra[r].z); p[3] = f2tf(ra[r].w);
        }
#pragma unroll
        for (int r = 0; r < 2; r++) {
            int n = bn + r * 32;
            sB[(bk + 0) * G2_SB_STRIDE + n] = f2tf(rb[r].x);
            sB[(bk + 1) * G2_SB_STRIDE + n] = f2tf(rb[r].y);
            sB[(bk + 2) * G2_SB_STRIDE + n] = f2tf(rb[r].z);
            sB[(bk + 3) * G2_SB_STRIDE + n] = f2tf(rb[r].w);
        }
        __syncthreads();
        if (k0 + 32 < CIN) {
#pragma unroll
            for (int r = 0; r < 4; r++)
                ra[r] = *(const float4*)(d_yb + (size_t)(m0 + am + r * 32) * CIN + k0 + 32 + akq);
#pragma unroll
            for (int r = 0; r < 2; r++)
                rb[r] = *(const float4*)(pw + (size_t)(n0 + bn + r * 32) * CIN + k0 + 32 + bk);
        }
#pragma unroll
        for (int kk = 0; kk < 32; kk += 8) {
            uint32_t a[2][4], bfr[4][2];
#pragma unroll
            for (int i = 0; i < 2; i++) {
                int row = wm + i * 16 + (lane >> 2);
                int kc  = kk + (lane & 3);
                a[i][0] = sA[row * G2_SA_STRIDE + kc];
                a[i][1] = sA[(row + 8) * G2_SA_STRIDE + kc];
                a[i][2] = sA[row * G2_SA_STRIDE + kc + 4];
                a[i][3] = sA[(row + 8) * G2_SA_STRIDE + kc + 4];
            }
#pragma unroll
            for (int j = 0; j < 4; j++) {
                int col = wn + j * 8 + (lane >> 2);
                int kr  = kk + (lane & 3);
                bfr[j][0] = sB[kr * G2_SB_STRIDE + col];
                bfr[j][1] = sB[(kr + 4) * G2_SB_STRIDE + col];
            }
#pragma unroll
            for (int i = 0; i < 2; i++)
#pragma unroll
                for (int j = 0; j < 4; j++)
                    mma_tf32(c[i][j], a[i], bfr[j]);
        }
        __syncthreads();
    }

    // stage C in smem for coalesced transposed output
    float* Cs = (float*)sh;   // [128][65]
#pragma unroll
    for (int i = 0; i < 2; i++) {
        int row = wm + i * 16 + (lane >> 2);
#pragma unroll
        for (int j = 0; j < 4; j++) {
            int col = wn + j * 8 + ((lane & 3) << 1);
            Cs[row * 65 + col]           = c[i][j][0];
            Cs[row * 65 + col + 1]       = c[i][j][1];
            Cs[(row + 8) * 65 + col]     = c[i][j][2];
            Cs[(row + 8) * 65 + col + 1] = c[i][j][3];
        }
    }
    __syncthreads();

    int mL = t & 127;
    int nh = (t >> 7) << 5;   // 0 or 32
    for (int nn = 0; nn < 32; nn++) {
        int n = nh + nn;
        out[(size_t)(b * CIN + n0 + n) * HW + hw0 + mL] = Cs[mL * 65 + n] + pb[n0 + n];
    }
}

// ---------------- launch -----------------------------------------------------
extern "C" void kernel_launch(void* const* d_in, const int* in_sizes, int n_in,
                              void* d_out, int out_size) {
    const float* x      = (const float*)d_in[0];
    const float* V_w    = (const float*)d_in[1];
    const float* V_b    = (const float*)d_in[2];
    const float* QK_w   = (const float*)d_in[3];
    const float* QK_b   = (const float*)d_in[4];
    const float* proj_w = (const float*)d_in[5];
    const float* proj_b = (const float*)d_in[6];
    const float* mw1    = (const float*)d_in[7];
    const float* mb1    = (const float*)d_in[8];
    const float* mw2    = (const float*)d_in[9];
    const float* mb2    = (const float*)d_in[10];
    float* out = (float*)d_out;

    fuse_w_kernel<<<(NQKV * CIN + 255) / 256, 256>>>(QK_w, QK_b, V_w, V_b);
    bias_kernel<<<(NWIN * NWIN + 255) / 256, 256>>>(mw1, mb1, mw2, mb2);
    gemm_qkv_tc<<<dim3(NQKV / 64, MTOT / 128), 256>>>(x);
    attn_kernel<<<dim3(2048, NH), 256>>>();
    gemm_proj_tc<<<dim3(CIN / 64, MTOT / 128), 256>>>(proj_w, proj_b, out);
}

// round 5
// speedup vs baseline: 1.8057x; 1.1841x over previous
#include <cuda_runtime.h>
#include <math.h>
#include <stdint.h>

// Problem constants
#define BATCH 8
#define CIN   192
#define HIMG  128
#define WIMG  128
#define HW    16384           // 128*128
#define MTOT  131072          // BATCH*HW
#define NQKV  576             // 3*C
#define NH    6
#define HD    32
#define WS    8
#define NWIN  64              // WS*WS
#define SCALE 0.17677669529663687f   // 32^-0.5

// ---------------- scratch (device globals; no runtime allocation) -----------
__device__ float d_qkv[(size_t)MTOT * NQKV];     // [pixel][576]  q|k|v channel-contig
__device__ float d_yb [(size_t)MTOT * CIN];      // [pixel][192]
__device__ float d_wfused[NQKV * CIN];           // [576][192]
__device__ float d_bfused[NQKV];
__device__ float d_biasT[NH * NWIN * NWIN];      // [head][n][m]

// ---------------- tf32 helpers ----------------------------------------------
__device__ __forceinline__ uint32_t f2tf(float f) {
    uint32_t u;
    asm("cvt.rna.tf32.f32 %0, %1;" : "=r"(u) : "f"(f));
    return u;
}

__device__ __forceinline__ void mma_tf32(float c[4], const uint32_t a[4], const uint32_t b[2]) {
    asm volatile(
        "mma.sync.aligned.m16n8k8.row.col.f32.tf32.tf32.f32 "
        "{%0,%1,%2,%3}, {%4,%5,%6,%7}, {%8,%9}, {%0,%1,%2,%3};"
        : "+f"(c[0]), "+f"(c[1]), "+f"(c[2]), "+f"(c[3])
        : "r"(a[0]), "r"(a[1]), "r"(a[2]), "r"(a[3]), "r"(b[0]), "r"(b[1]));
}

// ---------------- kernel 1: fuse QK_w/V_w into one weight matrix ------------
__global__ void fuse_w_kernel(const float* __restrict__ QK_w,
                              const float* __restrict__ QK_b,
                              const float* __restrict__ V_w,
                              const float* __restrict__ V_b) {
    int idx = blockIdx.x * blockDim.x + threadIdx.x;
    if (idx < NQKV * CIN) {
        int n = idx / CIN, k = idx - n * CIN;
        d_wfused[idx] = (n < 2 * CIN) ? QK_w[n * CIN + k] : V_w[(n - 2 * CIN) * CIN + k];
    }
    if (idx < NQKV) {
        d_bfused[idx] = (idx < 2 * CIN) ? QK_b[idx] : V_b[idx - 2 * CIN];
    }
}

// ---------------- kernel 2: relative-position bias via meta MLP -------------
__global__ void bias_kernel(const float* __restrict__ w1, const float* __restrict__ b1,
                            const float* __restrict__ w2, const float* __restrict__ b2) {
    int idx = blockIdx.x * 256 + threadIdx.x;   // 0..4095
    if (idx >= NWIN * NWIN) return;
    int n1 = idx >> 6, n2 = idx & 63;
    float di = (float)((n1 >> 3) - (n2 >> 3));
    float dj = (float)((n1 & 7) - (n2 & 7));
    float s0 = (di > 0.f) ? 1.f : ((di < 0.f) ? -1.f : 0.f);
    float s1 = (dj > 0.f) ? 1.f : ((dj < 0.f) ? -1.f : 0.f);
    float rp0 = s0 * log1pf(fabsf(di));
    float rp1 = s1 * log1pf(fabsf(dj));
    float acc[NH];
#pragma unroll
    for (int c = 0; c < NH; c++) acc[c] = b2[c];
    for (int t = 0; t < 256; t++) {
        float h = rp0 * w1[t] + rp1 * w1[256 + t] + b1[t];
        h = fmaxf(h, 0.f);
#pragma unroll
        for (int c = 0; c < NH; c++) acc[c] += h * w2[t * NH + c];
    }
#pragma unroll
    for (int c = 0; c < NH; c++)
        d_biasT[(c * NWIN + n1) * NWIN + n2] = acc[c];
}

// ---------------- kernel 3: GEMM1 (tf32 tensor core) ------------------------
#define G1_SA_STRIDE 136
#define G1_SB_STRIDE 72
__global__ void __launch_bounds__(256) gemm_qkv_tc(const float* __restrict__ x) {
    __shared__ __align__(16) uint32_t sh[32 * G1_SA_STRIDE + 32 * G1_SB_STRIDE];
    uint32_t* sA = sh;
    uint32_t* sB = sh + 32 * G1_SA_STRIDE;

    int m0 = blockIdx.y * 128;
    int n0 = blockIdx.x * 64;
    int b  = m0 >> 14;
    int hw0 = m0 & (HW - 1);
    const float* xb = x + (size_t)b * CIN * HW + hw0;

    int t = threadIdx.x;
    int lane = t & 31, warp = t >> 5;
    int wm = (warp >> 1) << 5;   // 0,32,64,96
    int wn = (warp & 1) << 5;    // 0,32

    int ak = t >> 5;             // k row 0..7 (+8r)
    int am = (t & 31) << 2;      // m vec
    int bn = t >> 3;             // n 0..31 (+32r)
    int bk = (t & 7) << 2;       // k vec

    float4 ra[4];
    float4 rb[2];
#pragma unroll
    for (int r = 0; r < 4; r++)
        ra[r] = *(const float4*)(xb + (size_t)(ak + r * 8) * HW + am);
#pragma unroll
    for (int r = 0; r < 2; r++)
        rb[r] = *(const float4*)(d_wfused + (size_t)(n0 + bn + r * 32) * CIN + bk);

    float c[2][4][4];
#pragma unroll
    for (int i = 0; i < 2; i++)
#pragma unroll
        for (int j = 0; j < 4; j++)
#pragma unroll
            for (int q = 0; q < 4; q++) c[i][j][q] = 0.f;

    for (int k0 = 0; k0 < CIN; k0 += 32) {
#pragma unroll
        for (int r = 0; r < 4; r++) {
            uint32_t* p = sA + (ak + r * 8) * G1_SA_STRIDE + am;
            p[0] = f2tf(ra[r].x); p[1] = f2tf(ra[r].y);
            p[2] = f2tf(ra[r].z); p[3] = f2tf(ra[r].w);
        }
#pragma unroll
        for (int r = 0; r < 2; r++) {
            int n = bn + r * 32;
            sB[(bk + 0) * G1_SB_STRIDE + n] = f2tf(rb[r].x);
            sB[(bk + 1) * G1_SB_STRIDE + n] = f2tf(rb[r].y);
            sB[(bk + 2) * G1_SB_STRIDE + n] = f2tf(rb[r].z);
            sB[(bk + 3) * G1_SB_STRIDE + n] = f2tf(rb[r].w);
        }
        __syncthreads();
        if (k0 + 32 < CIN) {
#pragma unroll
            for (int r = 0; r < 4; r++)
                ra[r] = *(const float4*)(xb + (size_t)(k0 + 32 + ak + r * 8) * HW + am);
#pragma unroll
            for (int r = 0; r < 2; r++)
                rb[r] = *(const float4*)(d_wfused + (size_t)(n0 + bn + r * 32) * CIN + k0 + 32 + bk);
        }
#pragma unroll
        for (int kk = 0; kk < 32; kk += 8) {
            uint32_t a[2][4], bfr[4][2];
#pragma unroll
            for (int i = 0; i < 2; i++) {
                int row = wm + i * 16 + (lane >> 2);
                int kc  = kk + (lane & 3);
                a[i][0] = sA[kc * G1_SA_STRIDE + row];
                a[i][1] = sA[kc * G1_SA_STRIDE + row + 8];
                a[i][2] = sA[(kc + 4) * G1_SA_STRIDE + row];
                a[i][3] = sA[(kc + 4) * G1_SA_STRIDE + row + 8];
            }
#pragma unroll
            for (int j = 0; j < 4; j++) {
                int col = wn + j * 8 + (lane >> 2);
                int kr  = kk + (lane & 3);
                bfr[j][0] = sB[kr * G1_SB_STRIDE + col];
                bfr[j][1] = sB[(kr + 4) * G1_SB_STRIDE + col];
            }
#pragma unroll
            for (int i = 0; i < 2; i++)
#pragma unroll
                for (int j = 0; j < 4; j++)
                    mma_tf32(c[i][j], a[i], bfr[j]);
        }
        __syncthreads();
    }

#pragma unroll
    for (int i = 0; i < 2; i++) {
        int row0 = m0 + wm + i * 16 + (lane >> 2);
#pragma unroll
        for (int j = 0; j < 4; j++) {
            int col = n0 + wn + j * 8 + ((lane & 3) << 1);
            float b0 = d_bfused[col], b1 = d_bfused[col + 1];
            float2 v0 = {c[i][j][0] + b0, c[i][j][1] + b1};
            float2 v1 = {c[i][j][2] + b0, c[i][j][3] + b1};
            *(float2*)&d_qkv[(size_t)row0 * NQKV + col] = v0;
            *(float2*)&d_qkv[(size_t)(row0 + 8) * NQKV + col] = v1;
        }
    }
}

// ---------------- kernel 4: attention with tensor-core logits/y -------------
// block = (window, head), 256 threads / 8 warps.
// smem (floats):
//   [0,4352)      qs[32][68] + ks[32][68]  -> reused as pnm[64][68] (tf32)
//   [4352,6528)   vdm[32][68]  v d-major (tf32): vdm[d*68+m]
//   [6528,8832)   vmd[64][36]  v m-major (tf32): vmd[m*36+d]
//   [8832,11136)  ond[64][36]  o n-major (tf32): ond[n*36+d]
//   [11136,11264) rmaxP[64][2]
//   [11264,11392) rsumP[64][2]
#define AT_QS   0
#define AT_KS   2176
#define AT_PNM  0
#define AT_VDM  4352
#define AT_VMD  6528
#define AT_OND  8832
#define AT_RMX  11136
#define AT_RSM  11264
#define AT_TOT  11392
__global__ void __launch_bounds__(256) attn_tc_kernel() {
    __shared__ __align__(16) float sh[AT_TOT];
    float* qs  = sh + AT_QS;
    float* ks  = sh + AT_KS;
    uint32_t* pnm = (uint32_t*)(sh + AT_PNM);
    uint32_t* vdm = (uint32_t*)(sh + AT_VDM);
    uint32_t* vmd = (uint32_t*)(sh + AT_VMD);
    uint32_t* ond = (uint32_t*)(sh + AT_OND);
    float* rmaxP = sh + AT_RMX;
    float* rsumP = sh + AT_RSM;

    int w_   = blockIdx.x;
    int head = blockIdx.y;
    int t = threadIdx.x;

    int b   = w_ >> 8;
    int rem = w_ & 255;
    int wi  = rem >> 4, wj = rem & 15;
    int base_pix = b * HW + wi * 8 * WIMG + wj * 8;
    int chq = head * HD;

    // ---- phase 1: load q,k,v ----
#pragma unroll
    for (int r = 0; r < 2; r++) {
        int idx = t + r * 256;             // 0..511
        int n  = idx >> 3;
        int dq = (idx & 7) << 2;           // 0,4,...,28
        int m = base_pix + ((n >> 3) * WIMG) + (n & 7);
        const float* p = d_qkv + (size_t)m * NQKV + chq + dq;
        float4 qv = *(const float4*)(p);
        float4 kv = *(const float4*)(p + CIN);
        float4 vv = *(const float4*)(p + 2 * CIN);
        qs[(dq + 0) * 68 + n] = qv.x * SCALE; qs[(dq + 1) * 68 + n] = qv.y * SCALE;
        qs[(dq + 2) * 68 + n] = qv.z * SCALE; qs[(dq + 3) * 68 + n] = qv.w * SCALE;
        ks[(dq + 0) * 68 + n] = kv.x; ks[(dq + 1) * 68 + n] = kv.y;
        ks[(dq + 2) * 68 + n] = kv.z; ks[(dq + 3) * 68 + n] = kv.w;
        uint32_t t0 = f2tf(vv.x), t1 = f2tf(vv.y), t2 = f2tf(vv.z), t3 = f2tf(vv.w);
        vdm[(dq + 0) * 68 + n] = t0; vdm[(dq + 1) * 68 + n] = t1;
        vdm[(dq + 2) * 68 + n] = t2; vdm[(dq + 3) * 68 + n] = t3;
        uint4 vm4 = {t0, t1, t2, t3};
        *(uint4*)&vmd[n * 36 + dq] = vm4;
    }
    __syncthreads();

    // ---- phase 2: 8x8 circular conv per channel (fp32) ----
    {
        int ci = t & 7;
        int d  = t >> 3;
        const float4* qrow = (const float4*)(qs + d * 68);
        const float4* krow = (const float4*)(ks + d * 68);
        float oacc[8];
#pragma unroll
        for (int j = 0; j < 8; j++) oacc[j] = 0.f;
#pragma unroll
        for (int ai = 0; ai < 8; ai++) {
            int ki = (ci - ai) & 7;
            float4 k0 = krow[ki * 2], k1 = krow[ki * 2 + 1];
            float kr[8] = {k0.x, k0.y, k0.z, k0.w, k1.x, k1.y, k1.z, k1.w};
            float4 q0 = qrow[ai * 2], q1 = qrow[ai * 2 + 1];
            float qv[8] = {q0.x, q0.y, q0.z, q0.w, q1.x, q1.y, q1.z, q1.w};
#pragma unroll
            for (int aj = 0; aj < 8; aj++) {
#pragma unroll
                for (int j = 0; j < 8; j++) oacc[j] += qv[aj] * kr[(j - aj) & 7];
            }
        }
#pragma unroll
        for (int j = 0; j < 8; j++)
            ond[(ci * 8 + j) * 36 + d] = f2tf(oacc[j]);
    }
    __syncthreads();

    // ---- phase 3: logits s = o @ v^T + bias via mma; softmax ----
    int lane = t & 31, w = t >> 5;
    int wr = w >> 1, wc = w & 1;      // 4x2 warp grid
    int n0w = wr * 16;
    int lr = lane >> 2, lc = lane & 3;

    uint32_t afr[4][4];
#pragma unroll
    for (int ksv = 0; ksv < 4; ksv++) {
        int kk = ksv * 8;
        afr[ksv][0] = ond[(n0w + lr) * 36 + kk + lc];
        afr[ksv][1] = ond[(n0w + lr + 8) * 36 + kk + lc];
        afr[ksv][2] = ond[(n0w + lr) * 36 + kk + lc + 4];
        afr[ksv][3] = ond[(n0w + lr + 8) * 36 + kk + lc + 4];
    }
    int m0w = wc * 32;
    float sacc[4][4];
#pragma unroll
    for (int mt = 0; mt < 4; mt++)
#pragma unroll
        for (int q = 0; q < 4; q++) sacc[mt][q] = 0.f;
#pragma unroll
    for (int mt = 0; mt < 4; mt++) {
        int mrow = m0w + mt * 8 + lr;
#pragma unroll
        for (int ksv = 0; ksv < 4; ksv++) {
            int kk = ksv * 8;
            uint32_t bf[2] = {vmd[mrow * 36 + kk + lc], vmd[mrow * 36 + kk + lc + 4]};
            mma_tf32(sacc[mt], afr[ksv], bf);
        }
    }
    // bias add
    {
        const float* bp = d_biasT + head * NWIN * NWIN;
#pragma unroll
        for (int mt = 0; mt < 4; mt++) {
            int col = m0w + mt * 8 + (lc << 1);
            float2 b0 = *(const float2*)(bp + (n0w + lr) * NWIN + col);
            float2 b1 = *(const float2*)(bp + (n0w + lr + 8) * NWIN + col);
            sacc[mt][0] += b0.x; sacc[mt][1] += b0.y;
            sacc[mt][2] += b1.x; sacc[mt][3] += b1.y;
        }
    }
    // row max (partial per warp-column)
    float mx0 = -1e30f, mx1 = -1e30f;
#pragma unroll
    for (int mt = 0; mt < 4; mt++) {
        mx0 = fmaxf(mx0, fmaxf(sacc[mt][0], sacc[mt][1]));
        mx1 = fmaxf(mx1, fmaxf(sacc[mt][2], sacc[mt][3]));
    }
    mx0 = fmaxf(mx0, __shfl_xor_sync(0xffffffffu, mx0, 1));
    mx0 = fmaxf(mx0, __shfl_xor_sync(0xffffffffu, mx0, 2));
    mx1 = fmaxf(mx1, __shfl_xor_sync(0xffffffffu, mx1, 1));
    mx1 = fmaxf(mx1, __shfl_xor_sync(0xffffffffu, mx1, 2));
    if (lc == 0) {
        rmaxP[(n0w + lr) * 2 + wc]     = mx0;
        rmaxP[(n0w + lr + 8) * 2 + wc] = mx1;
    }
    __syncthreads();
    float g0 = fmaxf(rmaxP[(n0w + lr) * 2],     rmaxP[(n0w + lr) * 2 + 1]);
    float g1 = fmaxf(rmaxP[(n0w + lr + 8) * 2], rmaxP[(n0w + lr + 8) * 2 + 1]);
    float s0 = 0.f, s1 = 0.f;
#pragma unroll
    for (int mt = 0; mt < 4; mt++) {
        float e0 = __expf(sacc[mt][0] - g0);
        float e1 = __expf(sacc[mt][1] - g0);
        float e2 = __expf(sacc[mt][2] - g1);
        float e3 = __expf(sacc[mt][3] - g1);
        s0 += e0 + e1; s1 += e2 + e3;
        int col = m0w + mt * 8 + (lc << 1);
        uint2 p0 = {f2tf(e0), f2tf(e1)};
        uint2 p1 = {f2tf(e2), f2tf(e3)};
        *(uint2*)&pnm[(n0w + lr) * 68 + col]     = p0;
        *(uint2*)&pnm[(n0w + lr + 8) * 68 + col] = p1;
    }
    s0 += __shfl_xor_sync(0xffffffffu, s0, 1);
    s0 += __shfl_xor_sync(0xffffffffu, s0, 2);
    s1 += __shfl_xor_sync(0xffffffffu, s1, 1);
    s1 += __shfl_xor_sync(0xffffffffu, s1, 2);
    if (lc == 0) {
        rsumP[(n0w + lr) * 2 + wc]     = s0;
        rsumP[(n0w + lr + 8) * 2 + wc] = s1;
    }
    __syncthreads();

    // ---- phase 5: y = p @ v (mma), normalize, store ----
    // y[n][d] = sum_m p[n][m] v[m][d]; B-frag b0 = v[m=kk+lc][d=dcol] = vdm[dcol*68 + kk+lc]
    int d0w = wc * 16;
    float yacc[2][4];
#pragma unroll
    for (int dt = 0; dt < 2; dt++)
#pragma unroll
        for (int q = 0; q < 4; q++) yacc[dt][q] = 0.f;
#pragma unroll
    for (int st = 0; st < 8; st++) {
        int kk = st * 8;
        uint32_t a[4] = {
            pnm[(n0w + lr) * 68 + kk + lc],
            pnm[(n0w + lr + 8) * 68 + kk + lc],
            pnm[(n0w + lr) * 68 + kk + lc + 4],
            pnm[(n0w + lr + 8) * 68 + kk + lc + 4]};
#pragma unroll
        for (int dt = 0; dt < 2; dt++) {
            int dcol = d0w + dt * 8 + lr;
            uint32_t bf[2] = {vdm[dcol * 68 + kk + lc], vdm[dcol * 68 + kk + lc + 4]};
            mma_tf32(yacc[dt], a, bf);
        }
    }
    {
        int r0 = n0w + lr, r1 = r0 + 8;
        float ri0 = 1.f / (rsumP[2 * r0] + rsumP[2 * r0 + 1]);
        float ri1 = 1.f / (rsumP[2 * r1] + rsumP[2 * r1 + 1]);
        int p0 = base_pix + ((r0 >> 3) * WIMG) + (r0 & 7);
        int p1 = base_pix + ((r1 >> 3) * WIMG) + (r1 & 7);
#pragma unroll
        for (int dt = 0; dt < 2; dt++) {
            int dc = d0w + dt * 8 + (lc << 1);
            float2 o0 = {yacc[dt][0] * ri0, yacc[dt][1] * ri0};
            float2 o1 = {yacc[dt][2] * ri1, yacc[dt][3] * ri1};
            *(float2*)&d_yb[(size_t)p0 * CIN + chq + dc] = o0;
            *(float2*)&d_yb[(size_t)p1 * CIN + chq + dc] = o1;
        }
    }
}

// ---------------- kernel 5: GEMM2 (tf32 tensor core) ------------------------
#define G2_SA_STRIDE 36
#define G2_SB_STRIDE 72
#define G2_SH_WORDS  8448
__global__ void __launch_bounds__(256) gemm_proj_tc(const float* __restrict__ pw,
                                                    const float* __restrict__ pb,
                                                    float* __restrict__ out) {
    __shared__ __align__(16) uint32_t sh[G2_SH_WORDS];
    uint32_t* sA = sh;
    uint32_t* sB = sh + 128 * G2_SA_STRIDE;

    int m0 = blockIdx.y * 128;
    int n0 = blockIdx.x * 64;
    int b  = m0 >> 14;
    int hw0 = m0 & (HW - 1);

    int t = threadIdx.x;
    int lane = t & 31, warp = t >> 5;
    int wm = (warp >> 1) << 5;
    int wn = (warp & 1) << 5;

    int am = t >> 3;
    int akq = (t & 7) << 2;
    int bn = t >> 3;
    int bk = (t & 7) << 2;

    float4 ra[4];
    float4 rb[2];
#pragma unroll
    for (int r = 0; r < 4; r++)
        ra[r] = *(const float4*)(d_yb + (size_t)(m0 + am + r * 32) * CIN + akq);
#pragma unroll
    for (int r = 0; r < 2; r++)
        rb[r] = *(const float4*)(pw + (size_t)(n0 + bn + r * 32) * CIN + bk);

    float c[2][4][4];
#pragma unroll
    for (int i = 0; i < 2; i++)
#pragma unroll
        for (int j = 0; j < 4; j++)
#pragma unroll
            for (int q = 0; q < 4; q++) c[i][j][q] = 0.f;

    for (int k0 = 0; k0 < CIN; k0 += 32) {
#pragma unroll
        for (int r = 0; r < 4; r++) {
            uint32_t* p = sA + (am + r * 32) * G2_SA_STRIDE + akq;
            p[0] = f2tf(ra[r].x); p[1] = f2tf(ra[r].y);
            p[2] = f2tf(ra[r].z); p[3] = f2tf(ra[r].w);
        }
#pragma unroll
        for (int r = 0; r < 2; r++) {
            int n = bn + r * 32;
            sB[(bk + 0) * G2_SB_STRIDE + n] = f2tf(rb[r].x);
            sB[(bk + 1) * G2_SB_STRIDE + n] = f2tf(rb[r].y);
            sB[(bk + 2) * G2_SB_STRIDE + n] = f2tf(rb[r].z);
            sB[(bk + 3) * G2_SB_STRIDE + n] = f2tf(rb[r].w);
        }
        __syncthreads();
        if (k0 + 32 < CIN) {
#pragma unroll
            for (int r = 0; r < 4; r++)
                ra[r] = *(const float4*)(d_yb + (size_t)(m0 + am + r * 32) * CIN + k0 + 32 + akq);
#pragma unroll
            for (int r = 0; r < 2; r++)
                rb[r] = *(const float4*)(pw + (size_t)(n0 + bn + r * 32) * CIN + k0 + 32 + bk);
        }
#pragma unroll
        for (int kk = 0; kk < 32; kk += 8) {
            uint32_t a[2][4], bfr[4][2];
#pragma unroll
            for (int i = 0; i < 2; i++) {
                int row = wm + i * 16 + (lane >> 2);
                int kc  = kk + (lane & 3);
                a[i][0] = sA[row * G2_SA_STRIDE + kc];
                a[i][1] = sA[(row + 8) * G2_SA_STRIDE + kc];
                a[i][2] = sA[row * G2_SA_STRIDE + kc + 4];
                a[i][3] = sA[(row + 8) * G2_SA_STRIDE + kc + 4];
            }
#pragma unroll
            for (int j = 0; j < 4; j++) {
                int col = wn + j * 8 + (lane >> 2);
                int kr  = kk + (lane & 3);
                bfr[j][0] = sB[kr * G2_SB_STRIDE + col];
                bfr[j][1] = sB[(kr + 4) * G2_SB_STRIDE + col];
            }
#pragma unroll
            for (int i = 0; i < 2; i++)
#pragma unroll
                for (int j = 0; j < 4; j++)
                    mma_tf32(c[i][j], a[i], bfr[j]);
        }
        __syncthreads();
    }

    float* Cs = (float*)sh;   // [128][65]
#pragma unroll
    for (int i = 0; i < 2; i++) {
        int row = wm + i * 16 + (lane >> 2);
#pragma unroll
        for (int j = 0; j < 4; j++) {
            int col = wn + j * 8 + ((lane & 3) << 1);
            Cs[row * 65 + col]           = c[i][j][0];
            Cs[row * 65 + col + 1]       = c[i][j][1];
            Cs[(row + 8) * 65 + col]     = c[i][j][2];
            Cs[(row + 8) * 65 + col + 1] = c[i][j][3];
        }
    }
    __syncthreads();

    int mL = t & 127;
    int nh = (t >> 7) << 5;
    for (int nn = 0; nn < 32; nn++) {
        int n = nh + nn;
        out[(size_t)(b * CIN + n0 + n) * HW + hw0 + mL] = Cs[mL * 65 + n] + pb[n0 + n];
    }
}

// ---------------- launch -----------------------------------------------------
extern "C" void kernel_launch(void* const* d_in, const int* in_sizes, int n_in,
                              void* d_out, int out_size) {
    const float* x      = (const float*)d_in[0];
    const float* V_w    = (const float*)d_in[1];
    const float* V_b    = (const float*)d_in[2];
    const float* QK_w   = (const float*)d_in[3];
    const float* QK_b   = (const float*)d_in[4];
    const float* proj_w = (const float*)d_in[5];
    const float* proj_b = (const float*)d_in[6];
    const float* mw1    = (const float*)d_in[7];
    const float* mb1    = (const float*)d_in[8];
    const float* mw2    = (const float*)d_in[9];
    const float* mb2    = (const float*)d_in[10];
    float* out = (float*)d_out;

    fuse_w_kernel<<<(NQKV * CIN + 255) / 256, 256>>>(QK_w, QK_b, V_w, V_b);
    bias_kernel<<<(NWIN * NWIN + 255) / 256, 256>>>(mw1, mb1, mw2, mb2);
    gemm_qkv_tc<<<dim3(NQKV / 64, MTOT / 128), 256>>>(x);
    attn_tc_kernel<<<dim3(2048, NH), 256>>>();
    gemm_proj_tc<<<dim3(CIN / 64, MTOT / 128), 256>>>(proj_w, proj_b, out);
}

// round 6
// speedup vs baseline: 2.0508x; 1.1357x over previous
#include <cuda_runtime.h>
#include <math.h>
#include <stdint.h>

// Problem constants
#define BATCH 8
#define CIN   192
#define HIMG  128
#define WIMG  128
#define HW    16384           // 128*128
#define MTOT  131072          // BATCH*HW
#define NQKV  576             // 3*C
#define NH    6
#define HD    32
#define WS    8
#define NWIN  64              // WS*WS
#define SCALE 0.17677669529663687f   // 32^-0.5

// ---------------- scratch (device globals; no runtime allocation) -----------
__device__ float d_qkv[(size_t)MTOT * NQKV];     // [pixel][576]  q|k|v channel-contig
__device__ float d_yb [(size_t)MTOT * CIN];      // [pixel][192]
__device__ float d_wfused[NQKV * CIN];           // [576][192]
__device__ float d_bfused[NQKV];
__device__ float d_biasT[NH * NWIN * NWIN];      // [head][n][m]

// ---------------- tf32 / async helpers ---------------------------------------
__device__ __forceinline__ uint32_t f2tf(float f) {
    uint32_t u;
    asm("cvt.rna.tf32.f32 %0, %1;" : "=r"(u) : "f"(f));
    return u;
}
__device__ __forceinline__ uint32_t f2tf_bits(uint32_t bits) {
    uint32_t u;
    asm("cvt.rna.tf32.f32 %0, %1;" : "=r"(u) : "f"(__uint_as_float(bits)));
    return u;
}

__device__ __forceinline__ void mma_tf32(float c[4], const uint32_t a[4], const uint32_t b[2]) {
    asm volatile(
        "mma.sync.aligned.m16n8k8.row.col.f32.tf32.tf32.f32 "
        "{%0,%1,%2,%3}, {%4,%5,%6,%7}, {%8,%9}, {%0,%1,%2,%3};"
        : "+f"(c[0]), "+f"(c[1]), "+f"(c[2]), "+f"(c[3])
        : "r"(a[0]), "r"(a[1]), "r"(a[2]), "r"(a[3]), "r"(b[0]), "r"(b[1]));
}

__device__ __forceinline__ void cp16(uint32_t saddr, const void* g) {
    asm volatile("cp.async.cg.shared.global [%0], [%1], 16;" :: "r"(saddr), "l"(g));
}
#define CP_COMMIT() asm volatile("cp.async.commit_group;")
#define CP_WAIT1()  asm volatile("cp.async.wait_group 1;")

// ---------------- kernel 1: fuse QK_w/V_w into one weight matrix ------------
__global__ void fuse_w_kernel(const float* __restrict__ QK_w,
                              const float* __restrict__ QK_b,
                              const float* __restrict__ V_w,
                              const float* __restrict__ V_b) {
    int idx = blockIdx.x * blockDim.x + threadIdx.x;
    if (idx < NQKV * CIN) {
        int n = idx / CIN, k = idx - n * CIN;
        d_wfused[idx] = (n < 2 * CIN) ? QK_w[n * CIN + k] : V_w[(n - 2 * CIN) * CIN + k];
    }
    if (idx < NQKV) {
        d_bfused[idx] = (idx < 2 * CIN) ? QK_b[idx] : V_b[idx - 2 * CIN];
    }
}

// ---------------- kernel 2: relative-position bias via meta MLP -------------
__global__ void bias_kernel(const float* __restrict__ w1, const float* __restrict__ b1,
                            const float* __restrict__ w2, const float* __restrict__ b2) {
    int idx = blockIdx.x * 256 + threadIdx.x;   // 0..4095
    if (idx >= NWIN * NWIN) return;
    int n1 = idx >> 6, n2 = idx & 63;
    float di = (float)((n1 >> 3) - (n2 >> 3));
    float dj = (float)((n1 & 7) - (n2 & 7));
    float s0 = (di > 0.f) ? 1.f : ((di < 0.f) ? -1.f : 0.f);
    float s1 = (dj > 0.f) ? 1.f : ((dj < 0.f) ? -1.f : 0.f);
    float rp0 = s0 * log1pf(fabsf(di));
    float rp1 = s1 * log1pf(fabsf(dj));
    float acc[NH];
#pragma unroll
    for (int c = 0; c < NH; c++) acc[c] = b2[c];
    for (int t = 0; t < 256; t++) {
        float h = rp0 * w1[t] + rp1 * w1[256 + t] + b1[t];
        h = fmaxf(h, 0.f);
#pragma unroll
        for (int c = 0; c < NH; c++) acc[c] += h * w2[t * NH + c];
    }
#pragma unroll
    for (int c = 0; c < NH; c++)
        d_biasT[(c * NWIN + n1) * NWIN + n2] = acc[c];
}

// ---------------- kernel 3: GEMM1 (tf32 TC, cp.async 3-stage) ---------------
// qkv[m][n] = sum_k x[b][k][hw] * Wfused[n][k] + bfused[n]
// M=131072, N=576, K=192. Tile 128x64, BK=16, 3 stages.
// sA [k][m] stride 136 (frag banks 8*lc+lr bijective), cp.async rows contiguous
// sB [n][k] stride 20  (frag banks 20*lr+lc bijective)
#define G1_SAS 136
#define G1_SBS 20
#define G1_SA_WORDS (16 * G1_SAS)      // 2176 per stage
#define G1_SB_WORDS (64 * G1_SBS)      // 1280 per stage
__global__ void __launch_bounds__(256) gemm_qkv_tc(const float* __restrict__ x) {
    __shared__ __align__(16) float sh[3 * G1_SA_WORDS + 3 * G1_SB_WORDS];  // 41.5 KB
    float* sAb = sh;
    float* sBb = sh + 3 * G1_SA_WORDS;
    uint32_t sA_s = (uint32_t)__cvta_generic_to_shared(sAb);
    uint32_t sB_s = (uint32_t)__cvta_generic_to_shared(sBb);

    int m0 = blockIdx.y * 128;
    int n0 = blockIdx.x * 64;
    int b  = m0 >> 14;
    int hw0 = m0 & (HW - 1);
    const float* xb = x + (size_t)b * CIN * HW + hw0;

    int t = threadIdx.x;
    int lane = t & 31, warp = t >> 5;
    int wm = (warp >> 1) << 5;   // 0,32,64,96
    int wn = (warp & 1) << 5;    // 0,32
    int lr = lane >> 2, lc = lane & 3;

    // A chunks: 2 per thread.  c = t + i*256: row = c>>5 (0..15), cm = (c&31)*4
    int a_row0 = t >> 5,        a_cm0 = (t & 31) << 2;
    int a_row1 = (t + 256) >> 5, a_cm1 = a_cm0;
    // B chunks: 1 per thread.  n = t>>2, kc = (t&3)*4
    int b_n = t >> 2, b_kc = (t & 3) << 2;

    float c[2][4][4];
#pragma unroll
    for (int i = 0; i < 2; i++)
#pragma unroll
        for (int j = 0; j < 4; j++)
#pragma unroll
            for (int q = 0; q < 4; q++) c[i][j][q] = 0.f;

#define G1_LOAD(stg, k0) do {                                                     \
        uint32_t dA = sA_s + ((stg) * G1_SA_WORDS) * 4;                           \
        cp16(dA + (a_row0 * G1_SAS + a_cm0) * 4, xb + (size_t)((k0) + a_row0) * HW + a_cm0); \
        cp16(dA + (a_row1 * G1_SAS + a_cm1) * 4, xb + (size_t)((k0) + a_row1) * HW + a_cm1); \
        uint32_t dB = sB_s + ((stg) * G1_SB_WORDS) * 4;                           \
        cp16(dB + (b_n * G1_SBS + b_kc) * 4, d_wfused + (size_t)(n0 + b_n) * CIN + (k0) + b_kc); \
    } while (0)

    G1_LOAD(0, 0);  CP_COMMIT();
    G1_LOAD(1, 16); CP_COMMIT();

    for (int it = 0; it < 12; it++) {
        CP_WAIT1();
        __syncthreads();
        int k0n = (it + 2) * 16;
        if (k0n < CIN) { G1_LOAD((it + 2) % 3, k0n); }
        CP_COMMIT();
        const uint32_t* sA = (const uint32_t*)(sAb + (it % 3) * G1_SA_WORDS);
        const uint32_t* sB = (const uint32_t*)(sBb + (it % 3) * G1_SB_WORDS);
#pragma unroll
        for (int kk = 0; kk < 16; kk += 8) {
            uint32_t a[2][4], bfr[4][2];
#pragma unroll
            for (int i = 0; i < 2; i++) {
                int row = wm + i * 16 + lr;
                a[i][0] = f2tf_bits(sA[(kk + lc) * G1_SAS + row]);
                a[i][1] = f2tf_bits(sA[(kk + lc) * G1_SAS + row + 8]);
                a[i][2] = f2tf_bits(sA[(kk + lc + 4) * G1_SAS + row]);
                a[i][3] = f2tf_bits(sA[(kk + lc + 4) * G1_SAS + row + 8]);
            }
#pragma unroll
            for (int j = 0; j < 4; j++) {
                int col = wn + j * 8 + lr;
                bfr[j][0] = f2tf_bits(sB[col * G1_SBS + kk + lc]);
                bfr[j][1] = f2tf_bits(sB[col * G1_SBS + kk + lc + 4]);
            }
#pragma unroll
            for (int i = 0; i < 2; i++)
#pragma unroll
                for (int j = 0; j < 4; j++)
                    mma_tf32(c[i][j], a[i], bfr[j]);
        }
    }

#pragma unroll
    for (int i = 0; i < 2; i++) {
        int row0 = m0 + wm + i * 16 + lr;
#pragma unroll
        for (int j = 0; j < 4; j++) {
            int col = n0 + wn + j * 8 + (lc << 1);
            float b0 = d_bfused[col], b1 = d_bfused[col + 1];
            float2 v0 = {c[i][j][0] + b0, c[i][j][1] + b1};
            float2 v1 = {c[i][j][2] + b0, c[i][j][3] + b1};
            *(float2*)&d_qkv[(size_t)row0 * NQKV + col] = v0;
            *(float2*)&d_qkv[(size_t)(row0 + 8) * NQKV + col] = v1;
        }
    }
}

// ---------------- kernel 4: attention with tensor-core logits/y -------------
// block = (window, head), 256 threads / 8 warps.
// smem (floats):
//   [0,4352)     qs[32][68] + ks[32][68]  -> reused as pnm[64][68] (tf32)
//   [4352,6528)  vdm[32][68]  v d-major (tf32): vdm[d*68+m]
//   [6528,8832)  ond[64][36]  o n-major (tf32): ond[n*36+d]
//   [8832,8960)  rmaxP[64][2]
//   [8960,9088)  rsumP[64][2]
#define AT_QS   0
#define AT_KS   2176
#define AT_PNM  0
#define AT_VDM  4352
#define AT_OND  6528
#define AT_RMX  8832
#define AT_RSM  8960
#define AT_TOT  9088
__global__ void __launch_bounds__(256) attn_tc_kernel() {
    __shared__ __align__(16) float sh[AT_TOT];
    float* qs  = sh + AT_QS;
    float* ks  = sh + AT_KS;
    uint32_t* pnm = (uint32_t*)(sh + AT_PNM);
    uint32_t* vdm = (uint32_t*)(sh + AT_VDM);
    uint32_t* ond = (uint32_t*)(sh + AT_OND);
    float* rmaxP = sh + AT_RMX;
    float* rsumP = sh + AT_RSM;

    int w_   = blockIdx.x;
    int head = blockIdx.y;
    int t = threadIdx.x;

    int b   = w_ >> 8;
    int rem = w_ & 255;
    int wi  = rem >> 4, wj = rem & 15;
    int base_pix = b * HW + wi * 8 * WIMG + wj * 8;
    int chq = head * HD;

    // ---- phase 1: load q,k,v ----
#pragma unroll
    for (int r = 0; r < 2; r++) {
        int idx = t + r * 256;             // 0..511
        int n  = idx >> 3;
        int dq = (idx & 7) << 2;           // 0,4,...,28
        int m = base_pix + ((n >> 3) * WIMG) + (n & 7);
        const float* p = d_qkv + (size_t)m * NQKV + chq + dq;
        float4 qv = *(const float4*)(p);
        float4 kv = *(const float4*)(p + CIN);
        float4 vv = *(const float4*)(p + 2 * CIN);
        qs[(dq + 0) * 68 + n] = qv.x * SCALE; qs[(dq + 1) * 68 + n] = qv.y * SCALE;
        qs[(dq + 2) * 68 + n] = qv.z * SCALE; qs[(dq + 3) * 68 + n] = qv.w * SCALE;
        ks[(dq + 0) * 68 + n] = kv.x; ks[(dq + 1) * 68 + n] = kv.y;
        ks[(dq + 2) * 68 + n] = kv.z; ks[(dq + 3) * 68 + n] = kv.w;
        vdm[(dq + 0) * 68 + n] = f2tf(vv.x); vdm[(dq + 1) * 68 + n] = f2tf(vv.y);
        vdm[(dq + 2) * 68 + n] = f2tf(vv.z); vdm[(dq + 3) * 68 + n] = f2tf(vv.w);
    }
    __syncthreads();

    // ---- phase 2: 8x8 circular conv per channel (fp32) ----
    {
        int ci = t & 7;
        int d  = t >> 3;
        const float4* qrow = (const float4*)(qs + d * 68);
        const float4* krow = (const float4*)(ks + d * 68);
        float oacc[8];
#pragma unroll
        for (int j = 0; j < 8; j++) oacc[j] = 0.f;
#pragma unroll
        for (int ai = 0; ai < 8; ai++) {
            int ki = (ci - ai) & 7;
            float4 k0 = krow[ki * 2], k1 = krow[ki * 2 + 1];
            float kr[8] = {k0.x, k0.y, k0.z, k0.w, k1.x, k1.y, k1.z, k1.w};
            float4 q0 = qrow[ai * 2], q1 = qrow[ai * 2 + 1];
            float qv[8] = {q0.x, q0.y, q0.z, q0.w, q1.x, q1.y, q1.z, q1.w};
#pragma unroll
            for (int aj = 0; aj < 8; aj++) {
#pragma unroll
                for (int j = 0; j < 8; j++) oacc[j] += qv[aj] * kr[(j - aj) & 7];
            }
        }
#pragma unroll
        for (int j = 0; j < 8; j++)
            ond[(ci * 8 + j) * 36 + d] = f2tf(oacc[j]);
    }
    __syncthreads();

    // ---- phase 3: logits s = o @ v^T + bias via mma; softmax ----
    int lane = t & 31, w = t >> 5;
    int wr = w >> 1, wc = w & 1;      // 4x2 warp grid
    int n0w = wr * 16;
    int lr = lane >> 2, lc = lane & 3;

    uint32_t afr[4][4];
#pragma unroll
    for (int ksv = 0; ksv < 4; ksv++) {
        int kk = ksv * 8;
        afr[ksv][0] = ond[(n0w + lr) * 36 + kk + lc];
        afr[ksv][1] = ond[(n0w + lr + 8) * 36 + kk + lc];
        afr[ksv][2] = ond[(n0w + lr) * 36 + kk + lc + 4];
        afr[ksv][3] = ond[(n0w + lr + 8) * 36 + kk + lc + 4];
    }
    int m0w = wc * 32;
    float sacc[4][4];
#pragma unroll
    for (int mt = 0; mt < 4; mt++)
#pragma unroll
        for (int q = 0; q < 4; q++) sacc[mt][q] = 0.f;
#pragma unroll
    for (int mt = 0; mt < 4; mt++) {
        int mrow = m0w + mt * 8 + lr;
#pragma unroll
        for (int ksv = 0; ksv < 4; ksv++) {
            int kk = ksv * 8;
            // B-frag from v d-major: b = v[m=mrow][d=kk+lc]
            uint32_t bf[2] = {vdm[(kk + lc) * 68 + mrow], vdm[(kk + lc + 4) * 68 + mrow]};
            mma_tf32(sacc[mt], afr[ksv], bf);
        }
    }
    // bias add
    {
        const float* bp = d_biasT + head * NWIN * NWIN;
#pragma unroll
        for (int mt = 0; mt < 4; mt++) {
            int col = m0w + mt * 8 + (lc << 1);
            float2 b0 = *(const float2*)(bp + (n0w + lr) * NWIN + col);
            float2 b1 = *(const float2*)(bp + (n0w + lr + 8) * NWIN + col);
            sacc[mt][0] += b0.x; sacc[mt][1] += b0.y;
            sacc[mt][2] += b1.x; sacc[mt][3] += b1.y;
        }
    }
    // row max (partial per warp-column)
    float mx0 = -1e30f, mx1 = -1e30f;
#pragma unroll
    for (int mt = 0; mt < 4; mt++) {
        mx0 = fmaxf(mx0, fmaxf(sacc[mt][0], sacc[mt][1]));
        mx1 = fmaxf(mx1, fmaxf(sacc[mt][2], sacc[mt][3]));
    }
    mx0 = fmaxf(mx0, __shfl_xor_sync(0xffffffffu, mx0, 1));
    mx0 = fmaxf(mx0, __shfl_xor_sync(0xffffffffu, mx0, 2));
    mx1 = fmaxf(mx1, __shfl_xor_sync(0xffffffffu, mx1, 1));
    mx1 = fmaxf(mx1, __shfl_xor_sync(0xffffffffu, mx1, 2));
    if (lc == 0) {
        rmaxP[(n0w + lr) * 2 + wc]     = mx0;
        rmaxP[(n0w + lr + 8) * 2 + wc] = mx1;
    }
    __syncthreads();
    float g0 = fmaxf(rmaxP[(n0w + lr) * 2],     rmaxP[(n0w + lr) * 2 + 1]);
    float g1 = fmaxf(rmaxP[(n0w + lr + 8) * 2], rmaxP[(n0w + lr + 8) * 2 + 1]);
    float s0 = 0.f, s1 = 0.f;
#pragma unroll
    for (int mt = 0; mt < 4; mt++) {
        float e0 = __expf(sacc[mt][0] - g0);
        float e1 = __expf(sacc[mt][1] - g0);
        float e2 = __expf(sacc[mt][2] - g1);
        float e3 = __expf(sacc[mt][3] - g1);
        s0 += e0 + e1; s1 += e2 + e3;
        int col = m0w + mt * 8 + (lc << 1);
        uint2 p0 = {f2tf(e0), f2tf(e1)};
        uint2 p1 = {f2tf(e2), f2tf(e3)};
        *(uint2*)&pnm[(n0w + lr) * 68 + col]     = p0;
        *(uint2*)&pnm[(n0w + lr + 8) * 68 + col] = p1;
    }
    s0 += __shfl_xor_sync(0xffffffffu, s0, 1);
    s0 += __shfl_xor_sync(0xffffffffu, s0, 2);
    s1 += __shfl_xor_sync(0xffffffffu, s1, 1);
    s1 += __shfl_xor_sync(0xffffffffu, s1, 2);
    if (lc == 0) {
        rsumP[(n0w + lr) * 2 + wc]     = s0;
        rsumP[(n0w + lr + 8) * 2 + wc] = s1;
    }
    __syncthreads();

    // ---- phase 5: y = p @ v (mma), normalize, store ----
    // y[n][d] = sum_m p[n][m] v[m][d]; b0 = v[m=kk+lc][d=dcol] = vdm[dcol*68 + kk+lc]
    int d0w = wc * 16;
    float yacc[2][4];
#pragma unroll
    for (int dt = 0; dt < 2; dt++)
#pragma unroll
        for (int q = 0; q < 4; q++) yacc[dt][q] = 0.f;
#pragma unroll
    for (int st = 0; st < 8; st++) {
        int kk = st * 8;
        uint32_t a[4] = {
            pnm[(n0w + lr) * 68 + kk + lc],
            pnm[(n0w + lr + 8) * 68 + kk + lc],
            pnm[(n0w + lr) * 68 + kk + lc + 4],
            pnm[(n0w + lr + 8) * 68 + kk + lc + 4]};
#pragma unroll
        for (int dt = 0; dt < 2; dt++) {
            int dcol = d0w + dt * 8 + lr;
            uint32_t bf[2] = {vdm[dcol * 68 + kk + lc], vdm[dcol * 68 + kk + lc + 4]};
            mma_tf32(yacc[dt], a, bf);
        }
    }
    {
        int r0 = n0w + lr, r1 = r0 + 8;
        float ri0 = 1.f / (rsumP[2 * r0] + rsumP[2 * r0 + 1]);
        float ri1 = 1.f / (rsumP[2 * r1] + rsumP[2 * r1 + 1]);
        int p0 = base_pix + ((r0 >> 3) * WIMG) + (r0 & 7);
        int p1 = base_pix + ((r1 >> 3) * WIMG) + (r1 & 7);
#pragma unroll
        for (int dt = 0; dt < 2; dt++) {
            int dc = d0w + dt * 8 + (lc << 1);
            float2 o0 = {yacc[dt][0] * ri0, yacc[dt][1] * ri0};
            float2 o1 = {yacc[dt][2] * ri1, yacc[dt][3] * ri1};
            *(float2*)&d_yb[(size_t)p0 * CIN + chq + dc] = o0;
            *(float2*)&d_yb[(size_t)p1 * CIN + chq + dc] = o1;
        }
    }
}

// ---------------- kernel 5: GEMM2 (tf32 TC, cp.async 3-stage) ---------------
// out[b][n][hw] = sum_k yb[m][k] * proj_w[n][k] + proj_b[n]
// M=131072, N=192, K=192. Tile 128x64, BK=16, 3 stages.
// sA [m][k] stride 20, sB [n][k] stride 20 (both: frag banks 20*lr+lc bijective)
#define G2_SS 20
#define G2_SA_WORDS (128 * G2_SS)    // 2560 per stage
#define G2_SB_WORDS (64 * G2_SS)     // 1280 per stage
__global__ void __launch_bounds__(256) gemm_proj_tc(const float* __restrict__ pw,
                                                    const float* __restrict__ pb,
                                                    float* __restrict__ out) {
    __shared__ __align__(16) float sh[3 * G2_SA_WORDS + 3 * G2_SB_WORDS];  // 46.1 KB
    float* sAb = sh;
    float* sBb = sh + 3 * G2_SA_WORDS;
    uint32_t sA_s = (uint32_t)__cvta_generic_to_shared(sAb);
    uint32_t sB_s = (uint32_t)__cvta_generic_to_shared(sBb);

    int m0 = blockIdx.y * 128;
    int n0 = blockIdx.x * 64;
    int b  = m0 >> 14;
    int hw0 = m0 & (HW - 1);

    int t = threadIdx.x;
    int lane = t & 31, warp = t >> 5;
    int wm = (warp >> 1) << 5;
    int wn = (warp & 1) << 5;
    int lr = lane >> 2, lc = lane & 3;

    // A chunks: 2 per thread. c = t + i*256: m = c>>2 (0..127), kc = (c&3)*4
    int a_m0 = t >> 2,          a_k0 = (t & 3) << 2;
    int a_m1 = (t + 256) >> 2,  a_k1 = a_k0;
    // B chunks: 1 per thread
    int b_n = t >> 2, b_kc = (t & 3) << 2;

    float c[2][4][4];
#pragma unroll
    for (int i = 0; i < 2; i++)
#pragma unroll
        for (int j = 0; j < 4; j++)
#pragma unroll
            for (int q = 0; q < 4; q++) c[i][j][q] = 0.f;

#define G2_LOAD(stg, k0) do {                                                     \
        uint32_t dA = sA_s + ((stg) * G2_SA_WORDS) * 4;                           \
        cp16(dA + (a_m0 * G2_SS + a_k0) * 4, d_yb + (size_t)(m0 + a_m0) * CIN + (k0) + a_k0); \
        cp16(dA + (a_m1 * G2_SS + a_k1) * 4, d_yb + (size_t)(m0 + a_m1) * CIN + (k0) + a_k1); \
        uint32_t dB = sB_s + ((stg) * G2_SB_WORDS) * 4;                           \
        cp16(dB + (b_n * G2_SS + b_kc) * 4, pw + (size_t)(n0 + b_n) * CIN + (k0) + b_kc); \
    } while (0)

    G2_LOAD(0, 0);  CP_COMMIT();
    G2_LOAD(1, 16); CP_COMMIT();

    for (int it = 0; it < 12; it++) {
        CP_WAIT1();
        __syncthreads();
        int k0n = (it + 2) * 16;
        if (k0n < CIN) { G2_LOAD((it + 2) % 3, k0n); }
        CP_COMMIT();
        const uint32_t* sA = (const uint32_t*)(sAb + (it % 3) * G2_SA_WORDS);
        const uint32_t* sB = (const uint32_t*)(sBb + (it % 3) * G2_SB_WORDS);
#pragma unroll
        for (int kk = 0; kk < 16; kk += 8) {
            uint32_t a[2][4], bfr[4][2];
#pragma unroll
            for (int i = 0; i < 2; i++) {
                int row = wm + i * 16 + lr;
                a[i][0] = f2tf_bits(sA[row * G2_SS + kk + lc]);
                a[i][1] = f2tf_bits(sA[(row + 8) * G2_SS + kk + lc]);
                a[i][2] = f2tf_bits(sA[row * G2_SS + kk + lc + 4]);
                a[i][3] = f2tf_bits(sA[(row + 8) * G2_SS + kk + lc + 4]);
            }
#pragma unroll
            for (int j = 0; j < 4; j++) {
                int col = wn + j * 8 + lr;
                bfr[j][0] = f2tf_bits(sB[col * G2_SS + kk + lc]);
                bfr[j][1] = f2tf_bits(sB[col * G2_SS + kk + lc + 4]);
            }
#pragma unroll
            for (int i = 0; i < 2; i++)
#pragma unroll
                for (int j = 0; j < 4; j++)
                    mma_tf32(c[i][j], a[i], bfr[j]);
        }
    }
    __syncthreads();

    // stage C in smem for coalesced transposed output
    float* Cs = sh;   // [128][65] = 8320 floats <= smem
#pragma unroll
    for (int i = 0; i < 2; i++) {
        int row = wm + i * 16 + lr;
#pragma unroll
        for (int j = 0; j < 4; j++) {
            int col = wn + j * 8 + (lc << 1);
            Cs[row * 65 + col]           = c[i][j][0];
            Cs[row * 65 + col + 1]       = c[i][j][1];
            Cs[(row + 8) * 65 + col]     = c[i][j][2];
            Cs[(row + 8) * 65 + col + 1] = c[i][j][3];
        }
    }
    __syncthreads();

    int mL = t & 127;
    int nh = (t >> 7) << 5;
    for (int nn = 0; nn < 32; nn++) {
        int n = nh + nn;
        out[(size_t)(b * CIN + n0 + n) * HW + hw0 + mL] = Cs[mL * 65 + n] + pb[n0 + n];
    }
}

// ---------------- launch -----------------------------------------------------
extern "C" void kernel_launch(void* const* d_in, const int* in_sizes, int n_in,
                              void* d_out, int out_size) {
    const float* x      = (const float*)d_in[0];
    const float* V_w    = (const float*)d_in[1];
    const float* V_b    = (const float*)d_in[2];
    const float* QK_w   = (const float*)d_in[3];
    const float* QK_b   = (const float*)d_in[4];
    const float* proj_w = (const float*)d_in[5];
    const float* proj_b = (const float*)d_in[6];
    const float* mw1    = (const float*)d_in[7];
    const float* mb1    = (const float*)d_in[8];
    const float* mw2    = (const float*)d_in[9];
    const float* mb2    = (const float*)d_in[10];
    float* out = (float*)d_out;

    fuse_w_kernel<<<(NQKV * CIN + 255) / 256, 256>>>(QK_w, QK_b, V_w, V_b);
    bias_kernel<<<(NWIN * NWIN + 255) / 256, 256>>>(mw1, mb1, mw2, mb2);
    gemm_qkv_tc<<<dim3(NQKV / 64, MTOT / 128), 256>>>(x);
    attn_tc_kernel<<<dim3(2048, NH), 256>>>();
    gemm_proj_tc<<<dim3(CIN / 64, MTOT / 128), 256>>>(proj_w, proj_b, out);
}

// round 8
// speedup vs baseline: 2.7302x; 1.3313x over previous
#include <cuda_runtime.h>
#include <cuda_fp16.h>
#include <math.h>
#include <stdint.h>

// Problem constants
#define BATCH 8
#define CIN   192
#define HIMG  128
#define WIMG  128
#define HW    16384           // 128*128
#define MTOT  131072          // BATCH*HW
#define NQKV  576             // 3*C
#define NH    6
#define HD    32
#define WS    8
#define NWIN  64              // WS*WS
#define SCALE 0.17677669529663687f   // 32^-0.5

// ---------------- scratch (device globals; no runtime allocation) -----------
__device__ __align__(16) unsigned short d_xh [(size_t)MTOT * CIN];   // x^T fp16 [m][c]
__device__ __align__(16) unsigned short d_qkv[(size_t)MTOT * NQKV];  // fp16 [m][576]
__device__ __align__(16) unsigned short d_yb [(size_t)MTOT * CIN];   // fp16 [m][192]
__device__ __align__(16) unsigned short d_wfh[NQKV * CIN];           // fp16 [576][192]
__device__ __align__(16) unsigned short d_pwh[CIN * CIN];            // fp16 [192][192]
__device__ float d_bfused[NQKV];
__device__ float d_biasT[NH * NWIN * NWIN];      // [head][n][m]

// ---------------- helpers ----------------------------------------------------
__device__ __forceinline__ void mma_f16(float c[4], const uint32_t a[4], const uint32_t b[2]) {
    asm volatile(
        "mma.sync.aligned.m16n8k16.row.col.f32.f16.f16.f32 "
        "{%0,%1,%2,%3}, {%4,%5,%6,%7}, {%8,%9}, {%0,%1,%2,%3};"
        : "+f"(c[0]), "+f"(c[1]), "+f"(c[2]), "+f"(c[3])
        : "r"(a[0]), "r"(a[1]), "r"(a[2]), "r"(a[3]), "r"(b[0]), "r"(b[1]));
}
__device__ __forceinline__ uint32_t pack2(float a, float b) {
    __half2 h = __floats2half2_rn(a, b);
    return *reinterpret_cast<uint32_t*>(&h);
}
__device__ __forceinline__ void cp16(uint32_t saddr, const void* g) {
    asm volatile("cp.async.cg.shared.global [%0], [%1], 16;" :: "r"(saddr), "l"(g));
}
#define CP_COMMIT() asm volatile("cp.async.commit_group;")
#define CP_WAIT1()  asm volatile("cp.async.wait_group 1;")

// ---------------- kernel 1: weight prep (fuse + fp16 convert) ---------------
__global__ void prep_w(const float* __restrict__ QK_w, const float* __restrict__ QK_b,
                       const float* __restrict__ V_w,  const float* __restrict__ V_b,
                       const float* __restrict__ pw) {
    int idx = blockIdx.x * 256 + threadIdx.x;
    if (idx < NQKV * CIN) {
        int n = idx / CIN, k = idx - n * CIN;
        float v = (n < 2 * CIN) ? QK_w[n * CIN + k] : V_w[(n - 2 * CIN) * CIN + k];
        d_wfh[idx] = __half_as_ushort(__float2half(v));
    }
    if (idx < CIN * CIN)
        d_pwh[idx] = __half_as_ushort(__float2half(pw[idx]));
    if (idx < NQKV)
        d_bfused[idx] = (idx < 2 * CIN) ? QK_b[idx] : V_b[idx - 2 * CIN];
}

// ---------------- kernel 2: relative-position bias via meta MLP -------------
__global__ void bias_kernel(const float* __restrict__ w1, const float* __restrict__ b1,
                            const float* __restrict__ w2, const float* __restrict__ b2) {
    int idx = blockIdx.x * 256 + threadIdx.x;   // 0..4095
    if (idx >= NWIN * NWIN) return;
    int n1 = idx >> 6, n2 = idx & 63;
    float di = (float)((n1 >> 3) - (n2 >> 3));
    float dj = (float)((n1 & 7) - (n2 & 7));
    float s0 = (di > 0.f) ? 1.f : ((di < 0.f) ? -1.f : 0.f);
    float s1 = (dj > 0.f) ? 1.f : ((dj < 0.f) ? -1.f : 0.f);
    float rp0 = s0 * log1pf(fabsf(di));
    float rp1 = s1 * log1pf(fabsf(dj));
    float acc[NH];
#pragma unroll
    for (int c = 0; c < NH; c++) acc[c] = b2[c];
    for (int t = 0; t < 256; t++) {
        float h = rp0 * w1[t] + rp1 * w1[256 + t] + b1[t];
        h = fmaxf(h, 0.f);
#pragma unroll
        for (int c = 0; c < NH; c++) acc[c] += h * w2[t * NH + c];
    }
#pragma unroll
    for (int c = 0; c < NH; c++)
        d_biasT[(c * NWIN + n1) * NWIN + n2] = acc[c];
}

// ---------------- kernel 3: transpose+convert x -> d_xh fp16 [m][c] ---------
__global__ void __launch_bounds__(256) transpose_x(const float* __restrict__ x) {
    __shared__ float tile[32][33];
    int cb = blockIdx.x << 5;
    int mb = blockIdx.y << 5;
    int b  = mb >> 14;
    int hw0 = mb & (HW - 1);
    int tx = threadIdx.x & 31, ty = threadIdx.x >> 5;
    const float* src = x + (size_t)b * CIN * HW + hw0;
#pragma unroll
    for (int i = 0; i < 4; i++)
        tile[ty + i * 8][tx] = src[(size_t)(cb + ty + i * 8) * HW + tx];
    __syncthreads();
#pragma unroll
    for (int i = 0; i < 4; i++) {
        int m = mb + ty + i * 8;
        d_xh[(size_t)m * CIN + cb + tx] =
            __half_as_ushort(__float2half(tile[tx][ty + i * 8]));
    }
}

// ---------------- GEMM common geometry ---------------------------------------
// fp16 m16n8k16, tiles 128x64, BK=32 halves (=16 half2 words), 3-stage cp.async
// smem rows: 16 data words + 4 pad = 20 words (banks 20*lr+lc bijective)
#define G_SS 20
#define G_SA_WORDS (128 * G_SS)      // 2560 words per stage
#define G_SB_WORDS (64 * G_SS)       // 1280 words per stage

// ---------------- kernel 4: GEMM1 qkv = xh @ wfh^T + b ----------------------
__global__ void __launch_bounds__(256) gemm_qkv_tc() {
    __shared__ __align__(16) uint32_t sh[3 * G_SA_WORDS + 3 * G_SB_WORDS];  // 45 KB
    uint32_t* sAb = sh;
    uint32_t* sBb = sh + 3 * G_SA_WORDS;
    uint32_t sA_s = (uint32_t)__cvta_generic_to_shared(sAb);
    uint32_t sB_s = (uint32_t)__cvta_generic_to_shared(sBb);

    int m0 = blockIdx.y * 128;
    int n0 = blockIdx.x * 64;
    int t = threadIdx.x;
    int lane = t & 31, warp = t >> 5;
    int wm = (warp >> 1) << 5, wn = (warp & 1) << 5;
    int lr = lane >> 2, lc = lane & 3;

    // A: 2 chunks/thread; chunk idx c: m=c>>2, kh=(c&3)*8 halves
    int a_m0 = t >> 2,         a_h0 = (t & 3) << 3;
    int a_m1 = (t + 256) >> 2, a_h1 = a_h0;
    int b_n = t >> 2,          b_h = (t & 3) << 3;

    float c[2][4][4];
#pragma unroll
    for (int i = 0; i < 2; i++)
#pragma unroll
        for (int j = 0; j < 4; j++)
#pragma unroll
            for (int q = 0; q < 4; q++) c[i][j][q] = 0.f;

#define G1L(stg, k0) do {                                                          \
        uint32_t dA = sA_s + ((stg) * G_SA_WORDS) * 4;                             \
        cp16(dA + (a_m0 * G_SS + (a_h0 >> 1)) * 4, d_xh + (size_t)(m0 + a_m0) * CIN + (k0) + a_h0); \
        cp16(dA + (a_m1 * G_SS + (a_h1 >> 1)) * 4, d_xh + (size_t)(m0 + a_m1) * CIN + (k0) + a_h1); \
        uint32_t dB = sB_s + ((stg) * G_SB_WORDS) * 4;                             \
        cp16(dB + (b_n * G_SS + (b_h >> 1)) * 4, d_wfh + (size_t)(n0 + b_n) * CIN + (k0) + b_h); \
    } while (0)

    G1L(0, 0);  CP_COMMIT();
    G1L(1, 32); CP_COMMIT();

    for (int it = 0; it < 6; it++) {
        CP_WAIT1();
        __syncthreads();
        int k0n = (it + 2) * 32;
        if (k0n < CIN) { G1L((it + 2) % 3, k0n); }
        CP_COMMIT();
        const uint32_t* sA = sAb + (it % 3) * G_SA_WORDS;
        const uint32_t* sB = sBb + (it % 3) * G_SB_WORDS;
#pragma unroll
        for (int ks = 0; ks < 2; ks++) {
            int kb = ks * 8;
            uint32_t a[2][4], bfr[4][2];
#pragma unroll
            for (int i = 0; i < 2; i++) {
                int row = wm + i * 16 + lr;
                a[i][0] = sA[row * G_SS + kb + lc];
                a[i][1] = sA[(row + 8) * G_SS + kb + lc];
                a[i][2] = sA[row * G_SS + kb + lc + 4];
                a[i][3] = sA[(row + 8) * G_SS + kb + lc + 4];
            }
#pragma unroll
            for (int j = 0; j < 4; j++) {
                int col = wn + j * 8 + lr;
                bfr[j][0] = sB[col * G_SS + kb + lc];
                bfr[j][1] = sB[col * G_SS + kb + lc + 4];
            }
#pragma unroll
            for (int i = 0; i < 2; i++)
#pragma unroll
                for (int j = 0; j < 4; j++)
                    mma_f16(c[i][j], a[i], bfr[j]);
        }
    }

#pragma unroll
    for (int i = 0; i < 2; i++) {
        int row0 = m0 + wm + i * 16 + lr;
#pragma unroll
        for (int j = 0; j < 4; j++) {
            int col = n0 + wn + j * 8 + (lc << 1);
            float b0 = d_bfused[col], b1 = d_bfused[col + 1];
            *(uint32_t*)&d_qkv[(size_t)row0 * NQKV + col] = pack2(c[i][j][0] + b0, c[i][j][1] + b1);
            *(uint32_t*)&d_qkv[(size_t)(row0 + 8) * NQKV + col] = pack2(c[i][j][2] + b0, c[i][j][3] + b1);
        }
    }
}

// ---------------- kernel 5: attention (fp16 mma) -----------------------------
// smem (float words):
//   [0,4352)     qs[32][68], ks[32][68] fp32    -> reused as pnm16 [64][36w]
//   [4352,5504)  vdm16 [d=32][36w] (72 halves: m-major within row)
//   [5504,6784)  vmd16 [m=64][20w] (40 halves: d)
//   [6784,8064)  ond16 [n=64][20w]
//   [8064,8192)  rmaxP[64][2]
//   [8192,8320)  rsumP[64][2]
#define AT_QS   0
#define AT_KS   2176
#define AT_PNM  0
#define AT_VDM  4352
#define AT_VMD  5504
#define AT_OND  6784
#define AT_RMX  8064
#define AT_RSM  8192
#define AT_TOT  8320
__global__ void __launch_bounds__(256) attn_tc_kernel() {
    __shared__ __align__(16) float sh[AT_TOT];
    float* qs = sh + AT_QS;
    float* ks = sh + AT_KS;
    uint32_t* pnm16 = (uint32_t*)(sh + AT_PNM);          // [n][36 words]
    uint32_t* vdm16 = (uint32_t*)(sh + AT_VDM);          // [d][36 words]
    unsigned short* vdm16h = (unsigned short*)vdm16;     // [d][72 halves]
    uint32_t* vmd16 = (uint32_t*)(sh + AT_VMD);          // [m][20 words]
    uint32_t* ond16 = (uint32_t*)(sh + AT_OND);          // [n][20 words]
    unsigned short* ond16h = (unsigned short*)ond16;     // [n][40 halves]
    float* rmaxP = sh + AT_RMX;
    float* rsumP = sh + AT_RSM;

    int w_   = blockIdx.x;
    int head = blockIdx.y;
    int t = threadIdx.x;

    int b   = w_ >> 8;
    int rem = w_ & 255;
    int wi  = rem >> 4, wj = rem & 15;
    int base_pix = b * HW + wi * 8 * WIMG + wj * 8;
    int chq = head * HD;

    // ---- phase 1: load q,k,v (fp16 global) ----
#pragma unroll
    for (int r = 0; r < 2; r++) {
        int idx = t + r * 256;             // 0..511
        int n  = idx >> 3;
        int dq = (idx & 7) << 2;           // 0,4,...,28
        int m = base_pix + ((n >> 3) * WIMG) + (n & 7);
        const unsigned short* p = d_qkv + (size_t)m * NQKV + chq + dq;
        uint2 qraw = *(const uint2*)p;
        uint2 kraw = *(const uint2*)(p + CIN);
        uint2 vraw = *(const uint2*)(p + 2 * CIN);
        float2 q01 = __half22float2(*reinterpret_cast<__half2*>(&qraw.x));
        float2 q23 = __half22float2(*reinterpret_cast<__half2*>(&qraw.y));
        float2 k01 = __half22float2(*reinterpret_cast<__half2*>(&kraw.x));
        float2 k23 = __half22float2(*reinterpret_cast<__half2*>(&kraw.y));
        qs[(dq + 0) * 68 + n] = q01.x * SCALE; qs[(dq + 1) * 68 + n] = q01.y * SCALE;
        qs[(dq + 2) * 68 + n] = q23.x * SCALE; qs[(dq + 3) * 68 + n] = q23.y * SCALE;
        ks[(dq + 0) * 68 + n] = k01.x; ks[(dq + 1) * 68 + n] = k01.y;
        ks[(dq + 2) * 68 + n] = k23.x; ks[(dq + 3) * 68 + n] = k23.y;
        // v d-major halves
        const unsigned short* vh = (const unsigned short*)&vraw;
        vdm16h[(dq + 0) * 72 + n] = vh[0];
        vdm16h[(dq + 1) * 72 + n] = vh[1];
        vdm16h[(dq + 2) * 72 + n] = vh[2];
        vdm16h[(dq + 3) * 72 + n] = vh[3];
        // v m-major words (d pairs) — raw copy
        vmd16[n * 20 + (dq >> 1)]     = vraw.x;
        vmd16[n * 20 + (dq >> 1) + 1] = vraw.y;
    }
    __syncthreads();

    // ---- phase 2: 8x8 circular conv per channel (fp32) ----
    {
        int ci = t & 7;
        int d  = t >> 3;
        const float4* qrow = (const float4*)(qs + d * 68);
        const float4* krow = (const float4*)(ks + d * 68);
        float oacc[8];
#pragma unroll
        for (int j = 0; j < 8; j++) oacc[j] = 0.f;
#pragma unroll
        for (int ai = 0; ai < 8; ai++) {
            int ki = (ci - ai) & 7;
            float4 k0 = krow[ki * 2], k1 = krow[ki * 2 + 1];
            float kr[8] = {k0.x, k0.y, k0.z, k0.w, k1.x, k1.y, k1.z, k1.w};
            float4 q0 = qrow[ai * 2], q1 = qrow[ai * 2 + 1];
            float qv[8] = {q0.x, q0.y, q0.z, q0.w, q1.x, q1.y, q1.z, q1.w};
#pragma unroll
            for (int aj = 0; aj < 8; aj++) {
#pragma unroll
                for (int j = 0; j < 8; j++) oacc[j] += qv[aj] * kr[(j - aj) & 7];
            }
        }
#pragma unroll
        for (int j = 0; j < 8; j++)
            ond16h[(ci * 8 + j) * 40 + d] = __half_as_ushort(__float2half(oacc[j]));
    }
    __syncthreads();

    // ---- phase 3: logits s = o @ v^T + bias (fp16 mma, K=32 = 2 ksteps) ----
    int lane = t & 31, w = t >> 5;
    int wr = w >> 1, wc = w & 1;      // 4x2 warp grid
    int n0w = wr * 16;
    int lr = lane >> 2, lc = lane & 3;

    uint32_t afr[2][4];
#pragma unroll
    for (int ksv = 0; ksv < 2; ksv++) {
        int kb = ksv * 8;
        afr[ksv][0] = ond16[(n0w + lr) * 20 + kb + lc];
        afr[ksv][1] = ond16[(n0w + lr + 8) * 20 + kb + lc];
        afr[ksv][2] = ond16[(n0w + lr) * 20 + kb + lc + 4];
        afr[ksv][3] = ond16[(n0w + lr + 8) * 20 + kb + lc + 4];
    }
    int m0w = wc * 32;
    float sacc[4][4];
#pragma unroll
    for (int mt = 0; mt < 4; mt++)
#pragma unroll
        for (int q = 0; q < 4; q++) sacc[mt][q] = 0.f;
#pragma unroll
    for (int mt = 0; mt < 4; mt++) {
        int mrow = m0w + mt * 8 + lr;
#pragma unroll
        for (int ksv = 0; ksv < 2; ksv++) {
            int kb = ksv * 8;
            uint32_t bf[2] = {vmd16[mrow * 20 + kb + lc], vmd16[mrow * 20 + kb + lc + 4]};
            mma_f16(sacc[mt], afr[ksv], bf);
        }
    }
    // bias add
    {
        const float* bp = d_biasT + head * NWIN * NWIN;
#pragma unroll
        for (int mt = 0; mt < 4; mt++) {
            int col = m0w + mt * 8 + (lc << 1);
            float2 b0 = *(const float2*)(bp + (n0w + lr) * NWIN + col);
            float2 b1 = *(const float2*)(bp + (n0w + lr + 8) * NWIN + col);
            sacc[mt][0] += b0.x; sacc[mt][1] += b0.y;
            sacc[mt][2] += b1.x; sacc[mt][3] += b1.y;
        }
    }
    // softmax (2-warp combine over m)
    float mx0 = -1e30f, mx1 = -1e30f;
#pragma unroll
    for (int mt = 0; mt < 4; mt++) {
        mx0 = fmaxf(mx0, fmaxf(sacc[mt][0], sacc[mt][1]));
        mx1 = fmaxf(mx1, fmaxf(sacc[mt][2], sacc[mt][3]));
    }
    mx0 = fmaxf(mx0, __shfl_xor_sync(0xffffffffu, mx0, 1));
    mx0 = fmaxf(mx0, __shfl_xor_sync(0xffffffffu, mx0, 2));
    mx1 = fmaxf(mx1, __shfl_xor_sync(0xffffffffu, mx1, 1));
    mx1 = fmaxf(mx1, __shfl_xor_sync(0xffffffffu, mx1, 2));
    if (lc == 0) {
        rmaxP[(n0w + lr) * 2 + wc]     = mx0;
        rmaxP[(n0w + lr + 8) * 2 + wc] = mx1;
    }
    __syncthreads();
    float g0 = fmaxf(rmaxP[(n0w + lr) * 2],     rmaxP[(n0w + lr) * 2 + 1]);
    float g1 = fmaxf(rmaxP[(n0w + lr + 8) * 2], rmaxP[(n0w + lr + 8) * 2 + 1]);
    float s0 = 0.f, s1 = 0.f;
#pragma unroll
    for (int mt = 0; mt < 4; mt++) {
        float e0 = __expf(sacc[mt][0] - g0);
        float e1 = __expf(sacc[mt][1] - g0);
        float e2 = __expf(sacc[mt][2] - g1);
        float e3 = __expf(sacc[mt][3] - g1);
        s0 += e0 + e1; s1 += e2 + e3;
        int colw = wc * 16 + mt * 4 + lc;   // word index of m-pair
        pnm16[(n0w + lr) * 36 + colw]     = pack2(e0, e1);
        pnm16[(n0w + lr + 8) * 36 + colw] = pack2(e2, e3);
    }
    s0 += __shfl_xor_sync(0xffffffffu, s0, 1);
    s0 += __shfl_xor_sync(0xffffffffu, s0, 2);
    s1 += __shfl_xor_sync(0xffffffffu, s1, 1);
    s1 += __shfl_xor_sync(0xffffffffu, s1, 2);
    if (lc == 0) {
        rsumP[(n0w + lr) * 2 + wc]     = s0;
        rsumP[(n0w + lr + 8) * 2 + wc] = s1;
    }
    __syncthreads();

    // ---- phase 5: y = p @ v (fp16 mma, K=64 = 4 ksteps), normalize, store ---
    int d0w = wc * 16;
    float yacc[2][4];
#pragma unroll
    for (int dt = 0; dt < 2; dt++)
#pragma unroll
        for (int q = 0; q < 4; q++) yacc[dt][q] = 0.f;
#pragma unroll
    for (int st = 0; st < 4; st++) {
        int kb = st * 8;
        uint32_t a[4] = {
            pnm16[(n0w + lr) * 36 + kb + lc],
            pnm16[(n0w + lr + 8) * 36 + kb + lc],
            pnm16[(n0w + lr) * 36 + kb + lc + 4],
            pnm16[(n0w + lr + 8) * 36 + kb + lc + 4]};
#pragma unroll
        for (int dt = 0; dt < 2; dt++) {
            int dcol = d0w + dt * 8 + lr;
            uint32_t bf[2] = {vdm16[dcol * 36 + kb + lc], vdm16[dcol * 36 + kb + lc + 4]};
            mma_f16(yacc[dt], a, bf);
        }
    }
    {
        int r0 = n0w + lr, r1 = r0 + 8;
        float ri0 = 1.f / (rsumP[2 * r0] + rsumP[2 * r0 + 1]);
        float ri1 = 1.f / (rsumP[2 * r1] + rsumP[2 * r1 + 1]);
        int p0 = base_pix + ((r0 >> 3) * WIMG) + (r0 & 7);
        int p1 = base_pix + ((r1 >> 3) * WIMG) + (r1 & 7);
#pragma unroll
        for (int dt = 0; dt < 2; dt++) {
            int dc = chq + d0w + dt * 8 + (lc << 1);
            *(uint32_t*)&d_yb[(size_t)p0 * CIN + dc] = pack2(yacc[dt][0] * ri0, yacc[dt][1] * ri0);
            *(uint32_t*)&d_yb[(size_t)p1 * CIN + dc] = pack2(yacc[dt][2] * ri1, yacc[dt][3] * ri1);
        }
    }
}

// ---------------- kernel 6: GEMM2 out = yb @ pwh^T + pb ---------------------
__global__ void __launch_bounds__(256) gemm_proj_tc(const float* __restrict__ pb,
                                                    float* __restrict__ out) {
    __shared__ __align__(16) uint32_t sh[3 * G_SA_WORDS + 3 * G_SB_WORDS];  // 45 KB
    uint32_t* sAb = sh;
    uint32_t* sBb = sh + 3 * G_SA_WORDS;
    uint32_t sA_s = (uint32_t)__cvta_generic_to_shared(sAb);
    uint32_t sB_s = (uint32_t)__cvta_generic_to_shared(sBb);

    int m0 = blockIdx.y * 128;
    int n0 = blockIdx.x * 64;
    int b  = m0 >> 14;
    int hw0 = m0 & (HW - 1);

    int t = threadIdx.x;
    int lane = t & 31, warp = t >> 5;
    int wm = (warp >> 1) << 5, wn = (warp & 1) << 5;
    int lr = lane >> 2, lc = lane & 3;

    int a_m0 = t >> 2,         a_h0 = (t & 3) << 3;
    int a_m1 = (t + 256) >> 2, a_h1 = a_h0;
    int b_n = t >> 2,          b_h = (t & 3) << 3;

    float c[2][4][4];
#pragma unroll
    for (int i = 0; i < 2; i++)
#pragma unroll
        for (int j = 0; j < 4; j++)
#pragma unroll
            for (int q = 0; q < 4; q++) c[i][j][q] = 0.f;

#define G2L(stg, k0) do {                                                          \
        uint32_t dA = sA_s + ((stg) * G_SA_WORDS) * 4;                             \
        cp16(dA + (a_m0 * G_SS + (a_h0 >> 1)) * 4, d_yb + (size_t)(m0 + a_m0) * CIN + (k0) + a_h0); \
        cp16(dA + (a_m1 * G_SS + (a_h1 >> 1)) * 4, d_yb + (size_t)(m0 + a_m1) * CIN + (k0) + a_h1); \
        uint32_t dB = sB_s + ((stg) * G_SB_WORDS) * 4;                             \
        cp16(dB + (b_n * G_SS + (b_h >> 1)) * 4, d_pwh + (size_t)(n0 + b_n) * CIN + (k0) + b_h); \
    } while (0)

    G2L(0, 0);  CP_COMMIT();
    G2L(1, 32); CP_COMMIT();

    for (int it = 0; it < 6; it++) {
        CP_WAIT1();
        __syncthreads();
        int k0n = (it + 2) * 32;
        if (k0n < CIN) { G2L((it + 2) % 3, k0n); }
        CP_COMMIT();
        const uint32_t* sA = sAb + (it % 3) * G_SA_WORDS;
        const uint32_t* sB = sBb + (it % 3) * G_SB_WORDS;
#pragma unroll
        for (int ks = 0; ks < 2; ks++) {
            int kb = ks * 8;
            uint32_t a[2][4], bfr[4][2];
#pragma unroll
            for (int i = 0; i < 2; i++) {
                int row = wm + i * 16 + lr;
                a[i][0] = sA[row * G_SS + kb + lc];
                a[i][1] = sA[(row + 8) * G_SS + kb + lc];
                a[i][2] = sA[row * G_SS + kb + lc + 4];
                a[i][3] = sA[(row + 8) * G_SS + kb + lc + 4];
            }
#pragma unroll
            for (int j = 0; j < 4; j++) {
                int col = wn + j * 8 + lr;
                bfr[j][0] = sB[col * G_SS + kb + lc];
                bfr[j][1] = sB[col * G_SS + kb + lc + 4];
            }
#pragma unroll
            for (int i = 0; i < 2; i++)
#pragma unroll
                for (int j = 0; j < 4; j++)
                    mma_f16(c[i][j], a[i], bfr[j]);
        }
    }
    __syncthreads();

    // stage C in smem for coalesced transposed output
    float* Cs = (float*)sh;   // [128][65] = 8320 floats (33.3 KB <= 45 KB)
#pragma unroll
    for (int i = 0; i < 2; i++) {
        int row = wm + i * 16 + lr;
#pragma unroll
        for (int j = 0; j < 4; j++) {
            int col = wn + j * 8 + (lc << 1);
            Cs[row * 65 + col]           = c[i][j][0];
            Cs[row * 65 + col + 1]       = c[i][j][1];
            Cs[(row + 8) * 65 + col]     = c[i][j][2];
            Cs[(row + 8) * 65 + col + 1] = c[i][j][3];
        }
    }
    __syncthreads();

    int mL = t & 127;
    int nh = (t >> 7) << 5;
    for (int nn = 0; nn < 32; nn++) {
        int n = nh + nn;
        out[(size_t)(b * CIN + n0 + n) * HW + hw0 + mL] = Cs[mL * 65 + n] + pb[n0 + n];
    }
}

// ---------------- launch -----------------------------------------------------
extern "C" void kernel_launch(void* const* d_in, const int* in_sizes, int n_in,
                              void* d_out, int out_size) {
    const float* x      = (const float*)d_in[0];
    const float* V_w    = (const float*)d_in[1];
    const float* V_b    = (const float*)d_in[2];
    const float* QK_w   = (const float*)d_in[3];
    const float* QK_b   = (const float*)d_in[4];
    const float* proj_w = (const float*)d_in[5];
    const float* proj_b = (const float*)d_in[6];
    const float* mw1    = (const float*)d_in[7];
    const float* mb1    = (const float*)d_in[8];
    const float* mw2    = (const float*)d_in[9];
    const float* mb2    = (const float*)d_in[10];
    float* out = (float*)d_out;

    prep_w<<<(NQKV * CIN + 255) / 256, 256>>>(QK_w, QK_b, V_w, V_b, proj_w);
    bias_kernel<<<(NWIN * NWIN + 255) / 256, 256>>>(mw1, mb1, mw2, mb2);
    transpose_x<<<dim3(CIN / 32, MTOT / 32), 256>>>(x);
    gemm_qkv_tc<<<dim3(NQKV / 64, MTOT / 128), 256>>>();
    attn_tc_kernel<<<dim3(2048, NH), 256>>>();
    gemm_proj_tc<<<dim3(CIN / 64, MTOT / 128), 256>>>(proj_b, out);
}